// round 1
// baseline (speedup 1.0000x reference)
#include <cuda_runtime.h>
#include <math.h>

#define Dv   128
#define Bv   4096
#define TILE 128

// Scratch (no allocations allowed): per-graph precomputed base rows + dtype flag.
__device__ float g_base[Bv * Dv];   // 2 MB
__device__ int   g_is64;

// ---------------------------------------------------------------------------
// batch dtype detection: values are sorted ints in [0,4096). If int64, word
// [C-1] (odd index) is the upper half of element (C-1)/2 == 0. If int32, it is
// batch[C-1] ~ 4095 != 0 (max of 1M uniform draws over 4096 bins).
// ---------------------------------------------------------------------------
__global__ void detect_kernel(const int* __restrict__ batch_words, int C) {
    g_is64 = (batch_words[C - 1] == 0) ? 1 : 0;
}

// ---------------------------------------------------------------------------
// Prep: base[b][d] = b1[d] + sum_k z_local[b][k]*W1[128+k][d]
//                          + sum_k z_meta[k]    *W1[256+k][d]
// 128 CTAs x 128 threads, 32 graphs per CTA. W1 rows 128..383 staged in SMEM.
// ---------------------------------------------------------------------------
__global__ void __launch_bounds__(128) prep_kernel(
    const float* __restrict__ z_local,
    const float* __restrict__ z_meta,
    const float* __restrict__ W1,
    const float* __restrict__ b1)
{
    extern __shared__ float sm[];
    float* Wp  = sm;                // 256*128 floats (W1 rows 128..383)
    float* zsh = sm + 256 * Dv;     // 256 floats: [z_local row | z_meta]

    const int tid = threadIdx.x;

    const float4* Wsrc = (const float4*)(W1 + Dv * Dv);
    float4* Wdst = (float4*)Wp;
    for (int i = tid; i < 256 * Dv / 4; i += 128) Wdst[i] = Wsrc[i];
    zsh[Dv + tid] = z_meta[tid];    // persistent meta half
    __syncthreads();

    const int b0 = blockIdx.x * 32;
    for (int g = 0; g < 32; ++g) {
        const int b = b0 + g;
        zsh[tid] = z_local[b * Dv + tid];
        __syncthreads();
        float acc = b1[tid];
        #pragma unroll 8
        for (int k = 0; k < 256; ++k)
            acc = fmaf(zsh[k], Wp[k * Dv + tid], acc);
        g_base[b * Dv + tid] = acc;
        __syncthreads();
    }
}

// ---------------------------------------------------------------------------
// Main: per CTA, a 128-node x 128-dim output tile of nodes @ W1a, fused with
// +base[batch[row]], exact GELU, dot with W2, and +b2. 256 threads, each
// computing an 8x8 register block. W1a (64 KB) and A tile (pitch 129, 64.5 KB)
// live in dynamic SMEM; the A buffer is reused for the 16-way row reduction.
// ---------------------------------------------------------------------------
__global__ void __launch_bounds__(256) main_kernel(
    const float* __restrict__ nodes,
    const float* __restrict__ W1,
    const float* __restrict__ W2,
    const float* __restrict__ b2,
    const void*  __restrict__ batch,
    float* __restrict__ out, int C)
{
    extern __shared__ float sm[];
    float* Wsh  = sm;                         // 128*128
    float* Ash  = sm + Dv * Dv;               // 128*129 (pitch 129: conflict-free)
    float* w2sh = Ash + TILE * 129;           // 128

    const int tid = threadIdx.x;
    const int tr  = tid >> 4;                 // 0..15 -> row group
    const int tc  = tid & 15;                 // 0..15 -> col group
    const int r0  = tr * 8;
    const int c0  = tc * 8;
    const int gr0 = blockIdx.x * TILE;
    int nrows = C - gr0; if (nrows > TILE) nrows = TILE;

    // Stage W1a (= first 128 rows of W1, contiguous) and w2.
    {
        const float4* src = (const float4*)W1;
        float4* dst = (float4*)Wsh;
        for (int i = tid; i < Dv * Dv / 4; i += 256) dst[i] = src[i];
        if (tid < Dv) w2sh[tid] = W2[tid];
    }
    // Stage A tile: coalesced float4 global reads, scalar SMEM stores (pitch 129).
    {
        const float4* nv = (const float4*)nodes;
        for (int idx = tid; idx < TILE * 32; idx += 256) {
            const int row = idx >> 5, k4 = idx & 31;
            float4 v = make_float4(0.f, 0.f, 0.f, 0.f);
            if (row < nrows) v = nv[(size_t)(gr0 + row) * 32 + k4];
            float* p = Ash + row * 129 + k4 * 4;
            p[0] = v.x; p[1] = v.y; p[2] = v.z; p[3] = v.w;
        }
    }
    __syncthreads();

    float acc[8][8];
    #pragma unroll
    for (int i = 0; i < 8; ++i)
        #pragma unroll
        for (int j = 0; j < 8; ++j) acc[i][j] = 0.f;

    #pragma unroll 4
    for (int k = 0; k < Dv; ++k) {
        float a[8], b[8];
        #pragma unroll
        for (int i = 0; i < 8; ++i) a[i] = Ash[(r0 + i) * 129 + k];
        const float4 b01 = *(const float4*)(Wsh + k * Dv + c0);
        const float4 b23 = *(const float4*)(Wsh + k * Dv + c0 + 4);
        b[0] = b01.x; b[1] = b01.y; b[2] = b01.z; b[3] = b01.w;
        b[4] = b23.x; b[5] = b23.y; b[6] = b23.z; b[7] = b23.w;
        #pragma unroll
        for (int i = 0; i < 8; ++i)
            #pragma unroll
            for (int j = 0; j < 8; ++j)
                acc[i][j] = fmaf(a[i], b[j], acc[i][j]);
    }

    __syncthreads();   // done reading Ash; reuse it as the reduction buffer

    const int is64 = g_is64;
    const int*       b32 = (const int*)batch;
    const long long* b64 = (const long long*)batch;
    float* red = Ash;  // [128][pitch 17]

    #pragma unroll
    for (int i = 0; i < 8; ++i) {
        const int row = r0 + i;
        const int gr  = gr0 + row;
        if (gr < C) {
            const int bi = is64 ? (int)b64[gr] : b32[gr];
            const float* basep = g_base + bi * Dv + c0;
            float partial = 0.f;
            #pragma unroll
            for (int j = 0; j < 8; ++j) {
                const float x = acc[i][j] + basep[j];
                const float gel = 0.5f * x * (1.0f + erff(x * 0.70710678118654752f));
                partial = fmaf(gel, w2sh[c0 + j], partial);
            }
            red[row * 17 + tc] = partial;
        }
    }
    __syncthreads();

    if (tid < TILE) {
        const int gr = gr0 + tid;
        if (gr < C) {
            float s = 0.f;
            #pragma unroll
            for (int t = 0; t < 16; ++t) s += red[tid * 17 + t];
            out[gr] = s + b2[0];
        }
    }
}

// ---------------------------------------------------------------------------
extern "C" void kernel_launch(void* const* d_in, const int* in_sizes, int n_in,
                              void* d_out, int out_size)
{
    const float* nodes   = (const float*)d_in[0];
    const float* z_local = (const float*)d_in[1];
    const float* z_meta  = (const float*)d_in[2];
    const float* W1      = (const float*)d_in[3];
    const float* b1      = (const float*)d_in[4];
    const float* W2      = (const float*)d_in[5];
    const float* b2      = (const float*)d_in[6];
    const void*  batch   = d_in[7];
    float* out = (float*)d_out;

    const int C = in_sizes[7];              // node count
    const int B = in_sizes[1] / Dv;         // graph count (4096)

    const int PREP_SMEM = (256 * Dv + 256) * (int)sizeof(float);          // 132096
    const int MAIN_SMEM = (Dv * Dv + TILE * 129 + Dv) * (int)sizeof(float); // 132096

    cudaFuncSetAttribute(prep_kernel, cudaFuncAttributeMaxDynamicSharedMemorySize, PREP_SMEM);
    cudaFuncSetAttribute(main_kernel, cudaFuncAttributeMaxDynamicSharedMemorySize, MAIN_SMEM);

    detect_kernel<<<1, 1>>>((const int*)batch, C);
    prep_kernel<<<B / 32, 128, PREP_SMEM>>>(z_local, z_meta, W1, b1);

    const int grid = (C + TILE - 1) / TILE;
    main_kernel<<<grid, 256, MAIN_SMEM>>>(nodes, W1, W2, b2, batch, out, C);
}

// round 3
// speedup vs baseline: 2.0328x; 2.0328x over previous
#include <cuda_runtime.h>
#include <math.h>

#define Dv   128
#define Bv   4096

// Scratch: per-graph precomputed base rows + batch dtype flag.
__device__ float g_base[Bv * Dv];   // 2 MB
__device__ int   g_is64;

// ---------------------------------------------------------------------------
// batch dtype detection (sorted ints in [0,4096)): word [C-1] is 0 iff int64.
// ---------------------------------------------------------------------------
__global__ void detect_kernel(const int* __restrict__ batch_words, int C) {
    g_is64 = (batch_words[C - 1] == 0) ? 1 : 0;
}

// ---------------------------------------------------------------------------
// Prep: base[b][d] = b1[d] + z_local[b]·W1[128:256] + z_meta·W1[256:384]
// ---------------------------------------------------------------------------
__global__ void __launch_bounds__(128) prep_kernel(
    const float* __restrict__ z_local,
    const float* __restrict__ z_meta,
    const float* __restrict__ W1,
    const float* __restrict__ b1)
{
    extern __shared__ float smem_f[];
    float* Wp  = smem_f;                // 256*128 floats (W1 rows 128..383)
    float* zsh = smem_f + 256 * Dv;     // 256 floats

    const int tid = threadIdx.x;

    const float4* Wsrc = (const float4*)(W1 + Dv * Dv);
    float4* Wdst = (float4*)Wp;
    for (int i = tid; i < 256 * Dv / 4; i += 128) Wdst[i] = Wsrc[i];
    zsh[Dv + tid] = z_meta[tid];
    __syncthreads();

    const int b0 = blockIdx.x * 32;
    for (int g = 0; g < 32; ++g) {
        const int b = b0 + g;
        zsh[tid] = z_local[b * Dv + tid];
        __syncthreads();
        float acc = b1[tid];
        #pragma unroll 8
        for (int k = 0; k < 256; ++k)
            acc = fmaf(zsh[k], Wp[k * Dv + tid], acc);
        g_base[b * Dv + tid] = acc;
        __syncthreads();
    }
}

// ---------------------------------------------------------------------------
// tf32 conversion (round-to-nearest)
// ---------------------------------------------------------------------------
__device__ __forceinline__ unsigned f2tf32(float x) {
    unsigned r;
    asm("cvt.rna.tf32.f32 %0, %1;" : "=r"(r) : "f"(x));
    return r;
}

// mma.sync m16n8k8 tf32: D += A*B, fp32 accum
#define MMA_TF32(c, av, bv)                                                    \
    asm volatile(                                                              \
        "mma.sync.aligned.m16n8k8.row.col.f32.tf32.tf32.f32 "                  \
        "{%0,%1,%2,%3}, {%4,%5,%6,%7}, {%8,%9}, {%0,%1,%2,%3};"                \
        : "+f"((c)[0]), "+f"((c)[1]), "+f"((c)[2]), "+f"((c)[3])               \
        : "r"((av).x), "r"((av).y), "r"((av).z), "r"((av).w),                  \
          "r"((bv).x), "r"((bv).y))

// SMEM word-offset layout (padded strides for conflict-free fragment reads)
#define AF_KS   1028    // Af stride per k8-step (4 wm * 2 tm * 128 + pad)
#define WF_NT   66      // Wf stride per n-tile (32 lanes * 2 regs + pad)
#define WF_KS   1056    // 16 n-tiles * WF_NT
#define AF_OFF  0
#define WF_OFF  16448   // 16 * AF_KS
#define W2_OFF  33344   // WF_OFF + 16 * WF_KS
#define RED_OFF 33472
#define SMEM_WORDS 33728

// ---------------------------------------------------------------------------
// Main: per CTA, 128-row x 128-col tile of nodes@W1a via tf32 mma.sync,
// fused +base[batch], exact GELU, dot(W2), +b2.
// 256 threads = 8 warps; warp tile 32(M) x 64(N); 16 k8-steps.
// A staged in two K-halves (reg-pipelined LDG overlap with first-half MMAs).
// ---------------------------------------------------------------------------
__global__ void __launch_bounds__(256, 1) main_kernel(
    const float* __restrict__ nodes,
    const float* __restrict__ W1,
    const float* __restrict__ W2,
    const float* __restrict__ b2,
    const void*  __restrict__ batch,
    float* __restrict__ out, int C)
{
    extern __shared__ float smem_f[];
    unsigned* smu  = (unsigned*)smem_f;
    unsigned* Af   = smu + AF_OFF;
    unsigned* Wf   = smu + WF_OFF;
    float*    w2sh = (float*)(smu + W2_OFF);
    float*    red  = (float*)(smu + RED_OFF);

    const int tid  = threadIdx.x;
    const int lane = tid & 31;
    const int warp = tid >> 5;
    const int wm   = warp >> 1;      // 0..3  -> rows wm*32
    const int wn   = warp & 1;       // 0..1  -> cols wn*64
    const int gr0  = blockIdx.x * 128;
    int nrows = C - gr0; if (nrows > 128) nrows = 128;

    // ---- stage W1a (rows 0..127 of W1) into fragment layout, tf32 ----
    {
        const float4* Wv = (const float4*)W1;
        for (int idx = tid; idx < 128 * 32; idx += 256) {
            const int k = idx >> 5, p = idx & 31;
            const float4 v = Wv[k * 32 + p];
            const int ks = k >> 3, reg = (k >> 2) & 1, kl = k & 3;
            const int n  = 4 * p;
            unsigned* dst = Wf + ks * WF_KS + (n >> 3) * WF_NT + reg;
            const int l0 = (n & 7) * 4 + kl;
            dst[(l0 + 0) * 2] = f2tf32(v.x);   // n+0
            dst[(l0 + 4) * 2] = f2tf32(v.y);   // n+1
            dst[(l0 + 8) * 2] = f2tf32(v.z);   // n+2
            dst[(l0 +12) * 2] = f2tf32(v.w);   // n+3
        }
        if (tid < 128) w2sh[tid] = W2[tid];
    }

    // ---- A staging (fragment layout, two k-halves) ----
    const float4* nv = (const float4*)nodes;
    float4 va[8], vb[8];

    // load half 0 (k 0..63)
    #pragma unroll
    for (int j = 0; j < 8; ++j) {
        const int e = j * 256 + tid, r = e >> 4, qq = e & 15;
        va[j] = (r < nrows) ? nv[(size_t)(gr0 + r) * 32 + qq]
                            : make_float4(0.f, 0.f, 0.f, 0.f);
    }
    // store half 0
    #pragma unroll
    for (int j = 0; j < 8; ++j) {
        const int e = j * 256 + tid, r = e >> 4, qq = e & 15;
        const int q = qq;
        const int ks = q >> 1, ch = q & 1;
        const int base = ks * AF_KS + (r >> 5) * 256 + ((r >> 4) & 1) * 128
                       + ((r >> 3) & 1) + 2 * ch;
        const int lb = (r & 7) * 4;
        Af[base + (lb + 0) * 4] = f2tf32(va[j].x);
        Af[base + (lb + 1) * 4] = f2tf32(va[j].y);
        Af[base + (lb + 2) * 4] = f2tf32(va[j].z);
        Af[base + (lb + 3) * 4] = f2tf32(va[j].w);
    }
    // issue half-1 loads (consumed after first MMA half -> latency hidden)
    #pragma unroll
    for (int j = 0; j < 8; ++j) {
        const int e = j * 256 + tid, r = e >> 4, qq = e & 15;
        vb[j] = (r < nrows) ? nv[(size_t)(gr0 + r) * 32 + 16 + qq]
                            : make_float4(0.f, 0.f, 0.f, 0.f);
    }
    __syncthreads();

    // ---- mainloop ----
    float acc[2][8][4];
    #pragma unroll
    for (int t = 0; t < 2; ++t)
        #pragma unroll
        for (int n = 0; n < 8; ++n)
            #pragma unroll
            for (int i = 0; i < 4; ++i) acc[t][n][i] = 0.f;

    const unsigned aoff = wm * 256 + lane * 4;
    const unsigned boff = wn * 8 * WF_NT + lane * 2;

    #pragma unroll 4
    for (int ks = 0; ks < 8; ++ks) {
        const uint4 a0 = *(const uint4*)&Af[ks * AF_KS + aoff];
        const uint4 a1 = *(const uint4*)&Af[ks * AF_KS + aoff + 128];
        uint2 bfr[8];
        #pragma unroll
        for (int nt = 0; nt < 8; ++nt)
            bfr[nt] = *(const uint2*)&Wf[ks * WF_KS + boff + nt * WF_NT];
        #pragma unroll
        for (int nt = 0; nt < 8; ++nt) {
            MMA_TF32(acc[0][nt], a0, bfr[nt]);
            MMA_TF32(acc[1][nt], a1, bfr[nt]);
        }
    }

    // store half 1 (k 64..127), then finish
    #pragma unroll
    for (int j = 0; j < 8; ++j) {
        const int e = j * 256 + tid, r = e >> 4, qq = e & 15;
        const int q = 16 + qq;
        const int ks = q >> 1, ch = q & 1;
        const int base = ks * AF_KS + (r >> 5) * 256 + ((r >> 4) & 1) * 128
                       + ((r >> 3) & 1) + 2 * ch;
        const int lb = (r & 7) * 4;
        Af[base + (lb + 0) * 4] = f2tf32(vb[j].x);
        Af[base + (lb + 1) * 4] = f2tf32(vb[j].y);
        Af[base + (lb + 2) * 4] = f2tf32(vb[j].z);
        Af[base + (lb + 3) * 4] = f2tf32(vb[j].w);
    }
    __syncthreads();

    #pragma unroll 4
    for (int ks = 8; ks < 16; ++ks) {
        const uint4 a0 = *(const uint4*)&Af[ks * AF_KS + aoff];
        const uint4 a1 = *(const uint4*)&Af[ks * AF_KS + aoff + 128];
        uint2 bfr[8];
        #pragma unroll
        for (int nt = 0; nt < 8; ++nt)
            bfr[nt] = *(const uint2*)&Wf[ks * WF_KS + boff + nt * WF_NT];
        #pragma unroll
        for (int nt = 0; nt < 8; ++nt) {
            MMA_TF32(acc[0][nt], a0, bfr[nt]);
            MMA_TF32(acc[1][nt], a1, bfr[nt]);
        }
    }

    // ---- fused epilogue: +base, GELU(exact), dot(w2), row-reduce ----
    const int is64 = g_is64;
    const int*       bt32 = (const int*)batch;
    const long long* bt64 = (const long long*)batch;

    #pragma unroll
    for (int tm = 0; tm < 2; ++tm) {
        #pragma unroll
        for (int rh = 0; rh < 2; ++rh) {
            const int row = wm * 32 + tm * 16 + rh * 8 + (lane >> 2);
            const int gr  = gr0 + row;
            float partial = 0.f;
            if (gr < C) {
                const int bi = is64 ? (int)bt64[gr] : bt32[gr];
                const float2* bp = (const float2*)(g_base + bi * Dv);
                #pragma unroll
                for (int nt = 0; nt < 8; ++nt) {
                    const int n0 = wn * 64 + nt * 8 + (lane & 3) * 2;
                    const float2 bv  = __ldg(bp + (n0 >> 1));
                    const float2 w2v = *(const float2*)(w2sh + n0);
                    const float x0 = acc[tm][nt][rh * 2 + 0] + bv.x;
                    const float x1 = acc[tm][nt][rh * 2 + 1] + bv.y;
                    const float g0 = 0.5f * x0 * (1.0f + erff(x0 * 0.70710678118654752f));
                    const float g1 = 0.5f * x1 * (1.0f + erff(x1 * 0.70710678118654752f));
                    partial = fmaf(g0, w2v.x, partial);
                    partial = fmaf(g1, w2v.y, partial);
                }
            }
            partial += __shfl_xor_sync(0xFFFFFFFFu, partial, 1);
            partial += __shfl_xor_sync(0xFFFFFFFFu, partial, 2);
            if ((lane & 3) == 0) red[row * 2 + wn] = partial;
        }
    }
    __syncthreads();

    if (tid < 128) {
        const int gr = gr0 + tid;
        if (gr < C) out[gr] = red[tid * 2] + red[tid * 2 + 1] + b2[0];
    }
}

// ---------------------------------------------------------------------------
extern "C" void kernel_launch(void* const* d_in, const int* in_sizes, int n_in,
                              void* d_out, int out_size)
{
    const float* nodes   = (const float*)d_in[0];
    const float* z_local = (const float*)d_in[1];
    const float* z_meta  = (const float*)d_in[2];
    const float* W1      = (const float*)d_in[3];
    const float* b1      = (const float*)d_in[4];
    const float* W2      = (const float*)d_in[5];
    const float* b2      = (const float*)d_in[6];
    const void*  batch   = d_in[7];
    float* out = (float*)d_out;

    const int C = in_sizes[7];
    const int B = in_sizes[1] / Dv;

    const int PREP_SMEM = (256 * Dv + 256) * (int)sizeof(float);
    const int MAIN_SMEM = SMEM_WORDS * (int)sizeof(unsigned);   // 134912 B

    cudaFuncSetAttribute(prep_kernel, cudaFuncAttributeMaxDynamicSharedMemorySize, PREP_SMEM);
    cudaFuncSetAttribute(main_kernel, cudaFuncAttributeMaxDynamicSharedMemorySize, MAIN_SMEM);

    detect_kernel<<<1, 1>>>((const int*)batch, C);
    prep_kernel<<<B / 32, 128, PREP_SMEM>>>(z_local, z_meta, W1, b1);

    const int grid = (C + 127) / 128;
    main_kernel<<<grid, 256, MAIN_SMEM>>>(nodes, W1, W2, b2, batch, out, C);
}

// round 5
// speedup vs baseline: 3.2302x; 1.5890x over previous
#include <cuda_runtime.h>
#include <math.h>
#include <stdint.h>

#define Dv   128
#define Bv   4096

// W fragment-layout constants (verified in R3)
#define WF_NT   66
#define WF_KS   1056
#define WF_WORDS (16 * WF_KS)   // 16896

// SMEM word layout (main kernel)
#define A_PITCH 132             // words per row (528B, 16B-aligned, conflict-free)
#define A_WORDS (128 * A_PITCH) // 16896
#define A0_OFF  0
#define A1_OFF  16896
#define WF_OFF  33792
#define W2_OFF  (WF_OFF + WF_WORDS)       // 50688
#define RED_OFF (W2_OFF + 128)            // 50816
#define SMEM_WORDS (RED_OFF + 256)        // 51072 -> 204288 B

// Scratch globals
__device__ float g_base[Bv * Dv];                 // per-graph base rows (2 MB)
__device__ __align__(16) float g_Wimg[WF_WORDS];  // prebuilt W1a fragment image
__device__ int   g_is64;

// ---------------- helpers ----------------
__device__ __forceinline__ uint32_t smem_u32(const void* p) {
    uint32_t a;
    asm("{ .reg .u64 t; cvta.to.shared.u64 t, %1; cvt.u32.u64 %0, t; }" : "=r"(a) : "l"(p));
    return a;
}
__device__ __forceinline__ unsigned f2tf32(float x) {
    unsigned r;
    asm("cvt.rna.tf32.f32 %0, %1;" : "=r"(r) : "f"(x));
    return r;
}
#define CP_ASYNC16(dst, src) \
    asm volatile("cp.async.cg.shared.global [%0], [%1], 16;" :: "r"(dst), "l"(src) : "memory")
#define CP_COMMIT() asm volatile("cp.async.commit_group;" ::: "memory")
#define CP_WAIT0()  asm volatile("cp.async.wait_group 0;" ::: "memory")

// mma.sync m16n8k8 tf32 (raw fp32 bits in a[], prebuilt tf32 in b)
#define MMA_TF32(c, a, bv)                                                     \
    asm volatile(                                                              \
        "mma.sync.aligned.m16n8k8.row.col.f32.tf32.tf32.f32 "                  \
        "{%0,%1,%2,%3}, {%4,%5,%6,%7}, {%8,%9}, {%0,%1,%2,%3};"                \
        : "+f"((c)[0]), "+f"((c)[1]), "+f"((c)[2]), "+f"((c)[3])               \
        : "r"((a)[0]), "r"((a)[1]), "r"((a)[2]), "r"((a)[3]),                  \
          "r"((bv).x), "r"((bv).y))

// ---------------------------------------------------------------------------
__global__ void detect_kernel(const int* __restrict__ batch_words, int C) {
    g_is64 = (batch_words[C - 1] == 0) ? 1 : 0;
}

// base[b][d] = b1[d] + z_local[b]·W1[128:256] + z_meta·W1[256:384]
__global__ void __launch_bounds__(128) prep_kernel(
    const float* __restrict__ z_local, const float* __restrict__ z_meta,
    const float* __restrict__ W1, const float* __restrict__ b1)
{
    extern __shared__ float smem_f[];
    float* Wp  = smem_f;
    float* zsh = smem_f + 256 * Dv;
    const int tid = threadIdx.x;

    const float4* Wsrc = (const float4*)(W1 + Dv * Dv);
    float4* Wdst = (float4*)Wp;
    for (int i = tid; i < 256 * Dv / 4; i += 128) Wdst[i] = Wsrc[i];
    zsh[Dv + tid] = z_meta[tid];
    __syncthreads();

    const int b0 = blockIdx.x * 32;
    for (int g = 0; g < 32; ++g) {
        const int b = b0 + g;
        zsh[tid] = z_local[b * Dv + tid];
        __syncthreads();
        float acc = b1[tid];
        #pragma unroll 8
        for (int k = 0; k < 256; ++k)
            acc = fmaf(zsh[k], Wp[k * Dv + tid], acc);
        g_base[b * Dv + tid] = acc;
        __syncthreads();
    }
}

// Prebuild W1a (rows 0..127 of W1) in mma B-fragment layout, tf32 rna. One CTA.
__global__ void __launch_bounds__(256) buildW_kernel(const float* __restrict__ W1) {
    const int tid = threadIdx.x;
    const float4* Wv = (const float4*)W1;
    unsigned* img = (unsigned*)g_Wimg;
    for (int idx = tid; idx < 128 * 32; idx += 256) {
        const int k = idx >> 5, p = idx & 31;
        const float4 v = Wv[k * 32 + p];
        const int ks = k >> 3, reg = (k >> 2) & 1, kl = k & 3;
        const int n  = 4 * p;
        unsigned* dst = img + ks * WF_KS + (n >> 3) * WF_NT + reg;
        const int l0 = (n & 7) * 4 + kl;
        dst[(l0 + 0) * 2] = f2tf32(v.x);
        dst[(l0 + 4) * 2] = f2tf32(v.y);
        dst[(l0 + 8) * 2] = f2tf32(v.z);
        dst[(l0 +12) * 2] = f2tf32(v.w);
    }
}

// ---------------------------------------------------------------------------
// Persistent main kernel: each CTA loops tiles (stride = gridDim), with A
// double-buffered via cp.async (next tile's copy overlaps current compute).
// W fragments staged once per CTA from the prebuilt global image (no cvt).
// ---------------------------------------------------------------------------
__global__ void __launch_bounds__(256, 1) main_kernel(
    const float* __restrict__ nodes,
    const float* __restrict__ W2,
    const float* __restrict__ b2,
    const void*  __restrict__ batch,
    float* __restrict__ out, int C, int T)
{
    extern __shared__ float smem_f[];
    const uint32_t smem_base = smem_u32(smem_f);
    const uint32_t* Au   = (const uint32_t*)smem_f;   // A buffers (word index)
    const unsigned* Wf   = (const unsigned*)(smem_f + WF_OFF);
    float* w2sh = smem_f + W2_OFF;
    float* red  = smem_f + RED_OFF;

    const int tid  = threadIdx.x;
    const int lane = tid & 31;
    const int warp = tid >> 5;
    const int wm   = warp >> 1;          // 0..3: rows wm*32
    const int wn   = warp & 1;           // 0..1: cols wn*64

    // ---- one-time W stage (linear copy of prebuilt image) ----
    {
        const float4* src = (const float4*)g_Wimg;
        float4* dst = (float4*)(smem_f + WF_OFF);
        #pragma unroll
        for (int j = 0; j < 17; ++j) {
            const int idx = j * 256 + tid;
            if (idx < WF_WORDS / 4) dst[idx] = src[idx];
        }
        if (tid < 128) w2sh[tid] = W2[tid];
    }
    const float b2v  = b2[0];
    const int   is64 = g_is64;
    const int*       bt32 = (const int*)batch;
    const long long* bt64 = (const long long*)batch;

    // ---- A stage issuer (cp.async, 16 chunks of 16B per thread) ----
    auto issueA = [&](int bufW, int t) {
        const int g0 = t * 128;
        int nr = C - g0; if (nr > 128) nr = 128;
        const char* src0 = (const char*)(nodes + (size_t)g0 * Dv);
        #pragma unroll
        for (int j = 0; j < 16; ++j) {
            const int e = j * 256 + tid;
            const int r = e >> 5, c = e & 31;
            if (r < nr) {
                const uint32_t dst = smem_base + (uint32_t)(bufW + r * A_PITCH + c * 4) * 4;
                CP_ASYNC16(dst, src0 + (size_t)r * 512 + c * 16);
            }
        }
    };

    const int aw0  = (wm * 32 + (lane >> 2)) * A_PITCH + (lane & 3);
    const int boff = wn * 8 * WF_NT + lane * 2;

    int tile = blockIdx.x;
    int p = 0;
    issueA(A0_OFF, tile);
    CP_COMMIT();

    for (; tile < T; tile += gridDim.x) {
        CP_WAIT0();
        __syncthreads();

        const int nxt = tile + gridDim.x;
        if (nxt < T) issueA(p ? A0_OFF : A1_OFF, nxt);
        CP_COMMIT();

        const int gr0 = tile * 128;

        // batch-index prefetch (4 rows/thread, epilogue mapping)
        int bidx[2][2];
        #pragma unroll
        for (int tm = 0; tm < 2; ++tm)
            #pragma unroll
            for (int rh = 0; rh < 2; ++rh) {
                const int gr = gr0 + wm * 32 + tm * 16 + rh * 8 + (lane >> 2);
                bidx[tm][rh] = (gr < C) ? (is64 ? (int)bt64[gr] : bt32[gr]) : 0;
            }

        // ---- mainloop ----
        float acc[2][8][4];
        #pragma unroll
        for (int t = 0; t < 2; ++t)
            #pragma unroll
            for (int n = 0; n < 8; ++n)
                #pragma unroll
                for (int i = 0; i < 4; ++i) acc[t][n][i] = 0.f;

        const uint32_t* Ab = Au + (p ? A1_OFF : A0_OFF);
        #pragma unroll 4
        for (int ks = 0; ks < 16; ++ks) {
            uint32_t a0[4], a1[4];
            const int o0 = aw0 + ks * 8;
            a0[0] = Ab[o0];            a0[1] = Ab[o0 + 8 * A_PITCH];
            a0[2] = Ab[o0 + 4];        a0[3] = Ab[o0 + 8 * A_PITCH + 4];
            const int o1 = o0 + 16 * A_PITCH;
            a1[0] = Ab[o1];            a1[1] = Ab[o1 + 8 * A_PITCH];
            a1[2] = Ab[o1 + 4];        a1[3] = Ab[o1 + 8 * A_PITCH + 4];
            uint2 bfr[8];
            #pragma unroll
            for (int nt = 0; nt < 8; ++nt)
                bfr[nt] = *(const uint2*)&Wf[ks * WF_KS + boff + nt * WF_NT];
            #pragma unroll
            for (int nt = 0; nt < 8; ++nt) {
                MMA_TF32(acc[0][nt], a0, bfr[nt]);
                MMA_TF32(acc[1][nt], a1, bfr[nt]);
            }
        }

        // ---- fused epilogue ----
        #pragma unroll
        for (int tm = 0; tm < 2; ++tm) {
            #pragma unroll
            for (int rh = 0; rh < 2; ++rh) {
                const int row = wm * 32 + tm * 16 + rh * 8 + (lane >> 2);
                const int gr  = gr0 + row;
                float partial = 0.f;
                if (gr < C) {
                    const float2* bp = (const float2*)(g_base + bidx[tm][rh] * Dv);
                    #pragma unroll
                    for (int nt = 0; nt < 8; ++nt) {
                        const int n0 = wn * 64 + nt * 8 + (lane & 3) * 2;
                        const float2 bv  = __ldg(bp + (n0 >> 1));
                        const float2 w2v = *(const float2*)(w2sh + n0);
                        const float x0 = acc[tm][nt][rh * 2 + 0] + bv.x;
                        const float x1 = acc[tm][nt][rh * 2 + 1] + bv.y;
                        const float g0 = 0.5f * x0 * (1.0f + erff(x0 * 0.70710678118654752f));
                        const float g1 = 0.5f * x1 * (1.0f + erff(x1 * 0.70710678118654752f));
                        partial = fmaf(g0, w2v.x, partial);
                        partial = fmaf(g1, w2v.y, partial);
                    }
                }
                partial += __shfl_xor_sync(0xFFFFFFFFu, partial, 1);
                partial += __shfl_xor_sync(0xFFFFFFFFu, partial, 2);
                if ((lane & 3) == 0) red[row * 2 + wn] = partial;
            }
        }
        __syncthreads();

        if (tid < 128) {
            const int g2 = gr0 + tid;
            if (g2 < C) out[g2] = red[tid * 2] + red[tid * 2 + 1] + b2v;
        }
        __syncthreads();
        p ^= 1;
    }
}

// ---------------------------------------------------------------------------
extern "C" void kernel_launch(void* const* d_in, const int* in_sizes, int n_in,
                              void* d_out, int out_size)
{
    const float* nodes   = (const float*)d_in[0];
    const float* z_local = (const float*)d_in[1];
    const float* z_meta  = (const float*)d_in[2];
    const float* W1      = (const float*)d_in[3];
    const float* b1      = (const float*)d_in[4];
    const float* W2      = (const float*)d_in[5];
    const float* b2      = (const float*)d_in[6];
    const void*  batch   = d_in[7];
    float* out = (float*)d_out;

    const int C = in_sizes[7];
    const int B = in_sizes[1] / Dv;
    const int T = (C + 127) / 128;

    int dev = 0, nsm = 148;
    cudaGetDevice(&dev);
    cudaDeviceGetAttribute(&nsm, cudaDevAttrMultiProcessorCount, dev);

    const int PREP_SMEM = (256 * Dv + 256) * (int)sizeof(float);   // 132096
    const int MAIN_SMEM = SMEM_WORDS * (int)sizeof(float);         // 204288

    cudaFuncSetAttribute(prep_kernel, cudaFuncAttributeMaxDynamicSharedMemorySize, PREP_SMEM);
    cudaFuncSetAttribute(main_kernel, cudaFuncAttributeMaxDynamicSharedMemorySize, MAIN_SMEM);

    detect_kernel<<<1, 1>>>((const int*)batch, C);
    prep_kernel<<<B / 32, 128, PREP_SMEM>>>(z_local, z_meta, W1, b1);
    buildW_kernel<<<1, 256>>>(W1);

    main_kernel<<<nsm, 256, MAIN_SMEM>>>(nodes, W2, b2, batch, out, C, T);
}

// round 6
// speedup vs baseline: 3.8581x; 1.1944x over previous
#include <cuda_runtime.h>
#include <math.h>
#include <stdint.h>

#define Dv   128
#define Bv   4096

// SMEM word layout (main kernel): pitch-132 rows (528B) for A and Wt
#define A_PITCH 132
#define A_WORDS (128 * A_PITCH)           // 16896
#define A0_OFF  0
#define A1_OFF  16896
#define WT_OFF  33792                     // Wt: 128 rows x pitch 132
#define W2_OFF  (WT_OFF + A_WORDS)        // 50688
#define RED_OFF (W2_OFF + 128)            // 50816
#define SMEM_WORDS (RED_OFF + 256)        // 51072 -> 204288 B

// Scratch globals
__device__ float g_base[Bv * Dv];                  // per-graph base rows (2 MB)
__device__ __align__(16) float g_Wt[128 * 128];    // W1a^T, tf32-rna bits
__device__ int   g_is64;

// ---------------- helpers ----------------
__device__ __forceinline__ uint32_t smem_u32(const void* p) {
    uint32_t a;
    asm("{ .reg .u64 t; cvta.to.shared.u64 t, %1; cvt.u32.u64 %0, t; }" : "=r"(a) : "l"(p));
    return a;
}
__device__ __forceinline__ unsigned f2tf32(float x) {
    unsigned r;
    asm("cvt.rna.tf32.f32 %0, %1;" : "=r"(r) : "f"(x));
    return r;
}
#define CP_ASYNC16(dst, src) \
    asm volatile("cp.async.cg.shared.global [%0], [%1], 16;" :: "r"(dst), "l"(src) : "memory")
#define CP_COMMIT() asm volatile("cp.async.commit_group;" ::: "memory")
#define CP_WAIT0()  asm volatile("cp.async.wait_group 0;" ::: "memory")

#define LDSM_X4(r0, r1, r2, r3, addr)                                          \
    asm volatile("ldmatrix.sync.aligned.m8n8.x4.shared.b16 {%0,%1,%2,%3}, [%4];" \
        : "=r"(r0), "=r"(r1), "=r"(r2), "=r"(r3) : "r"(addr))

// mma.sync m16n8k8 tf32
#define MMA_TF32(c, a, b0, b1)                                                 \
    asm volatile(                                                              \
        "mma.sync.aligned.m16n8k8.row.col.f32.tf32.tf32.f32 "                  \
        "{%0,%1,%2,%3}, {%4,%5,%6,%7}, {%8,%9}, {%0,%1,%2,%3};"                \
        : "+f"((c)[0]), "+f"((c)[1]), "+f"((c)[2]), "+f"((c)[3])               \
        : "r"((a)[0]), "r"((a)[1]), "r"((a)[2]), "r"((a)[3]),                  \
          "r"(b0), "r"(b1))

// gelu(x) = x * sigmoid(x*(2.3021204 + 0.1029356 x^2))  [tanh-form, branch-free]
__device__ __forceinline__ float gelu_fast(float x) {
    const float x2 = x * x;
    const float zn = x * fmaf(-0.102935562f, x2, -2.3021205f);
    float t, r;
    asm("ex2.approx.f32 %0, %1;" : "=f"(t) : "f"(zn));
    asm("rcp.approx.f32 %0, %1;" : "=f"(r) : "f"(1.0f + t));
    return x * r;
}

// ---------------------------------------------------------------------------
// aux: blocks 0..63 build Wt (tf32-rna transpose of W1 rows 0..127);
//      block 64 detects batch dtype (word [C-1] is 0 iff int64).
// ---------------------------------------------------------------------------
__global__ void __launch_bounds__(256) aux_kernel(const float* __restrict__ W1,
                                                  const int* __restrict__ batch_words,
                                                  int C) {
    if (blockIdx.x == 64) {
        if (threadIdx.x == 0) g_is64 = (batch_words[C - 1] == 0) ? 1 : 0;
        return;
    }
    const int idx = blockIdx.x * 256 + threadIdx.x;   // 16384
    const int n = idx >> 7, k = idx & 127;
    g_Wt[n * 128 + k] = __uint_as_float(f2tf32(W1[k * Dv + n]));
}

// base[b][d] = b1[d] + z_local[b]·W1[128:256] + z_meta·W1[256:384]
__global__ void __launch_bounds__(128) prep_kernel(
    const float* __restrict__ z_local, const float* __restrict__ z_meta,
    const float* __restrict__ W1, const float* __restrict__ b1)
{
    extern __shared__ float smem_f[];
    float* Wp  = smem_f;
    float* zsh = smem_f + 256 * Dv;
    const int tid = threadIdx.x;

    const float4* Wsrc = (const float4*)(W1 + Dv * Dv);
    float4* Wdst = (float4*)Wp;
    for (int i = tid; i < 256 * Dv / 4; i += 128) Wdst[i] = Wsrc[i];
    zsh[Dv + tid] = z_meta[tid];
    __syncthreads();

    const int b0 = blockIdx.x * 32;
    for (int g = 0; g < 32; ++g) {
        const int b = b0 + g;
        zsh[tid] = z_local[b * Dv + tid];
        __syncthreads();
        float acc = b1[tid];
        #pragma unroll 8
        for (int k = 0; k < 256; ++k)
            acc = fmaf(zsh[k], Wp[k * Dv + tid], acc);
        g_base[b * Dv + tid] = acc;
        __syncthreads();
    }
}

// ---------------------------------------------------------------------------
// Persistent main kernel. A double-buffered via cp.async; A and B fragments
// fed to tf32 mma via ldmatrix.x4.b16 (identity k-mapping for f32-as-b16x2).
// ---------------------------------------------------------------------------
__global__ void __launch_bounds__(256, 1) main_kernel(
    const float* __restrict__ nodes,
    const float* __restrict__ W2,
    const float* __restrict__ b2,
    const void*  __restrict__ batch,
    float* __restrict__ out, int C, int T)
{
    extern __shared__ float smem_f[];
    const uint32_t smem_base = smem_u32(smem_f);
    float* w2sh = smem_f + W2_OFF;
    float* red  = smem_f + RED_OFF;

    const int tid  = threadIdx.x;
    const int lane = tid & 31;
    const int warp = tid >> 5;
    const int wm   = warp >> 1;          // 0..3: rows wm*32
    const int wn   = warp & 1;           // 0..1: cols wn*64

    // ---- one-time Wt stage: rows n, pitch 132 ----
    {
        const float4* src = (const float4*)g_Wt;
        for (int idx = tid; idx < 4096; idx += 256) {
            const int r = idx >> 5, c = idx & 31;
            *(float4*)(smem_f + WT_OFF + r * A_PITCH + c * 4) = src[idx];
        }
        if (tid < 128) w2sh[tid] = W2[tid];
    }
    const float b2v  = b2[0];
    const int   is64 = g_is64;
    const int*       bt32 = (const int*)batch;
    const long long* bt64 = (const long long*)batch;

    // ---- ldmatrix lane addresses ----
    // A (per m16 tile tm): matrices {R..R+7,q0},{R+8..R+15,q0},{..,q1},{..,q1}
    const int rowA = wm * 32 + ((lane >> 3) & 1) * 8 + (lane & 7);
    const uint32_t aoffA = (uint32_t)(rowA * A_PITCH) * 4 + (lane >> 4) * 16;
    // B pair p (nt=2p,2p+1): matrices {n..n+7,q0},{..,q1},{n+8..n+15,q0},{..,q1}
    const int nB = wn * 64 + ((lane >> 4) & 1) * 8 + (lane & 7);
    uint32_t bAdr[4];
    #pragma unroll
    for (int p = 0; p < 4; ++p)
        bAdr[p] = smem_base + (uint32_t)(WT_OFF + (nB + p * 16) * A_PITCH) * 4
                + ((lane >> 3) & 1) * 16;

    // ---- A stage issuer (cp.async, 16B chunks, row-major pitch 132) ----
    auto issueA = [&](int bufW, int t) {
        const int g0 = t * 128;
        int nr = C - g0; if (nr > 128) nr = 128;
        const char* src0 = (const char*)(nodes + (size_t)g0 * Dv);
        #pragma unroll
        for (int j = 0; j < 16; ++j) {
            const int e = j * 256 + tid;
            const int r = e >> 5, c = e & 31;
            if (r < nr) {
                const uint32_t dst = smem_base + (uint32_t)(bufW + r * A_PITCH + c * 4) * 4;
                CP_ASYNC16(dst, src0 + (size_t)r * 512 + c * 16);
            }
        }
    };

    int tile = blockIdx.x;
    int p = 0;
    issueA(A0_OFF, tile);
    CP_COMMIT();

    for (; tile < T; tile += gridDim.x) {
        CP_WAIT0();
        __syncthreads();

        const int nxt = tile + gridDim.x;
        if (nxt < T) issueA(p ? A0_OFF : A1_OFF, nxt);
        CP_COMMIT();

        const int gr0 = tile * 128;

        // batch-index prefetch (epilogue row mapping)
        int bidx[2][2];
        #pragma unroll
        for (int tm = 0; tm < 2; ++tm)
            #pragma unroll
            for (int rh = 0; rh < 2; ++rh) {
                const int gr = gr0 + wm * 32 + tm * 16 + rh * 8 + (lane >> 2);
                bidx[tm][rh] = (gr < C) ? (is64 ? (int)bt64[gr] : bt32[gr]) : 0;
            }

        // ---- mainloop ----
        float acc[2][8][4];
        #pragma unroll
        for (int t = 0; t < 2; ++t)
            #pragma unroll
            for (int n = 0; n < 8; ++n)
                #pragma unroll
                for (int i = 0; i < 4; ++i) acc[t][n][i] = 0.f;

        const uint32_t aBase = smem_base + (uint32_t)(p ? A1_OFF : A0_OFF) * 4 + aoffA;

        #pragma unroll 4
        for (int ks = 0; ks < 16; ++ks) {
            uint32_t a0[4], a1[4], bf[4][4];
            LDSM_X4(a0[0], a0[1], a0[2], a0[3], aBase + ks * 32);
            LDSM_X4(a1[0], a1[1], a1[2], a1[3], aBase + ks * 32 + 16 * A_PITCH * 4);
            #pragma unroll
            for (int q = 0; q < 4; ++q)
                LDSM_X4(bf[q][0], bf[q][1], bf[q][2], bf[q][3], bAdr[q] + ks * 32);
            #pragma unroll
            for (int q = 0; q < 4; ++q) {
                MMA_TF32(acc[0][2 * q + 0], a0, bf[q][0], bf[q][1]);
                MMA_TF32(acc[1][2 * q + 0], a1, bf[q][0], bf[q][1]);
                MMA_TF32(acc[0][2 * q + 1], a0, bf[q][2], bf[q][3]);
                MMA_TF32(acc[1][2 * q + 1], a1, bf[q][2], bf[q][3]);
            }
        }

        // ---- fused epilogue: +base, fast GELU, w2 dot, row-reduce ----
        #pragma unroll
        for (int tm = 0; tm < 2; ++tm) {
            #pragma unroll
            for (int rh = 0; rh < 2; ++rh) {
                const int row = wm * 32 + tm * 16 + rh * 8 + (lane >> 2);
                const int gr  = gr0 + row;
                float partial = 0.f;
                if (gr < C) {
                    const float2* bp = (const float2*)(g_base + bidx[tm][rh] * Dv);
                    #pragma unroll
                    for (int nt = 0; nt < 8; ++nt) {
                        const int n0 = wn * 64 + nt * 8 + (lane & 3) * 2;
                        const float2 bv  = __ldg(bp + (n0 >> 1));
                        const float2 w2v = *(const float2*)(w2sh + n0);
                        const float x0 = acc[tm][nt][rh * 2 + 0] + bv.x;
                        const float x1 = acc[tm][nt][rh * 2 + 1] + bv.y;
                        partial = fmaf(gelu_fast(x0), w2v.x, partial);
                        partial = fmaf(gelu_fast(x1), w2v.y, partial);
                    }
                }
                partial += __shfl_xor_sync(0xFFFFFFFFu, partial, 1);
                partial += __shfl_xor_sync(0xFFFFFFFFu, partial, 2);
                if ((lane & 3) == 0) red[row * 2 + wn] = partial;
            }
        }
        __syncthreads();

        if (tid < 128) {
            const int g2 = gr0 + tid;
            if (g2 < C) out[g2] = red[tid * 2] + red[tid * 2 + 1] + b2v;
        }
        __syncthreads();
        p ^= 1;
    }
}

// ---------------------------------------------------------------------------
extern "C" void kernel_launch(void* const* d_in, const int* in_sizes, int n_in,
                              void* d_out, int out_size)
{
    const float* nodes   = (const float*)d_in[0];
    const float* z_local = (const float*)d_in[1];
    const float* z_meta  = (const float*)d_in[2];
    const float* W1      = (const float*)d_in[3];
    const float* b1      = (const float*)d_in[4];
    const float* W2      = (const float*)d_in[5];
    const float* b2      = (const float*)d_in[6];
    const void*  batch   = d_in[7];
    float* out = (float*)d_out;

    const int C = in_sizes[7];
    const int B = in_sizes[1] / Dv;
    const int T = (C + 127) / 128;

    int dev = 0, nsm = 148;
    cudaGetDevice(&dev);
    cudaDeviceGetAttribute(&nsm, cudaDevAttrMultiProcessorCount, dev);

    const int PREP_SMEM = (256 * Dv + 256) * (int)sizeof(float);   // 132096
    const int MAIN_SMEM = SMEM_WORDS * (int)sizeof(float);         // 204288

    cudaFuncSetAttribute(prep_kernel, cudaFuncAttributeMaxDynamicSharedMemorySize, PREP_SMEM);
    cudaFuncSetAttribute(main_kernel, cudaFuncAttributeMaxDynamicSharedMemorySize, MAIN_SMEM);

    aux_kernel<<<65, 256>>>(W1, (const int*)batch, C);
    prep_kernel<<<B / 32, 128, PREP_SMEM>>>(z_local, z_meta, W1, b1);

    main_kernel<<<nsm, 256, MAIN_SMEM>>>(nodes, W2, b2, batch, out, C, T);
}

// round 8
// speedup vs baseline: 4.6782x; 1.2126x over previous
#include <cuda_runtime.h>
#include <math.h>
#include <stdint.h>

#define Dv   128
#define Bv   4096

// SMEM word layout (main kernel): pitch-132 rows (528B) for A and Wt
#define A_PITCH 132
#define A_WORDS (128 * A_PITCH)           // 16896
#define A0_OFF  0
#define A1_OFF  16896
#define WT_OFF  33792                     // Wt: 128 rows x pitch 132
#define W2_OFF  (WT_OFF + A_WORDS)        // 50688
#define RED_OFF (W2_OFF + 128)            // 50816
#define SMEM_WORDS (RED_OFF + 256)        // 51072 -> 204288 B

// Scratch globals
__device__ float g_base[Bv * Dv];                  // per-graph base rows (2 MB)
__device__ __align__(16) float g_Wt[128 * 128];    // W1a^T, tf32-rna bits
__device__ int   g_is64;

// ---------------- helpers ----------------
__device__ __forceinline__ uint32_t smem_u32(const void* p) {
    uint32_t a;
    asm("{ .reg .u64 t; cvta.to.shared.u64 t, %1; cvt.u32.u64 %0, t; }" : "=r"(a) : "l"(p));
    return a;
}
__device__ __forceinline__ unsigned f2tf32(float x) {
    unsigned r;
    asm("cvt.rna.tf32.f32 %0, %1;" : "=r"(r) : "f"(x));
    return r;
}
#define CP_ASYNC16(dst, src) \
    asm volatile("cp.async.cg.shared.global [%0], [%1], 16;" :: "r"(dst), "l"(src) : "memory")
#define CP_COMMIT() asm volatile("cp.async.commit_group;" ::: "memory")
#define CP_WAIT0()  asm volatile("cp.async.wait_group 0;" ::: "memory")

#define LDSM_X4(r0, r1, r2, r3, addr)                                          \
    asm volatile("ldmatrix.sync.aligned.m8n8.x4.shared.b16 {%0,%1,%2,%3}, [%4];" \
        : "=r"(r0), "=r"(r1), "=r"(r2), "=r"(r3) : "r"(addr))

// mma.sync m16n8k8 tf32
#define MMA_TF32(c, a, b0, b1)                                                 \
    asm volatile(                                                              \
        "mma.sync.aligned.m16n8k8.row.col.f32.tf32.tf32.f32 "                  \
        "{%0,%1,%2,%3}, {%4,%5,%6,%7}, {%8,%9}, {%0,%1,%2,%3};"                \
        : "+f"((c)[0]), "+f"((c)[1]), "+f"((c)[2]), "+f"((c)[3])               \
        : "r"((a)[0]), "r"((a)[1]), "r"((a)[2]), "r"((a)[3]),                  \
          "r"(b0), "r"(b1))

// gelu(x) = 0.5x(1+tanh(0.79788456x + 0.03567741x^3))  -- single MUFU tanh
__device__ __forceinline__ float gelu_fast(float x) {
    const float z = x * fmaf(0.035677408f, x * x, 0.7978845608f);
    float t;
    asm("tanh.approx.f32 %0, %1;" : "=f"(t) : "f"(z));
    const float hx = 0.5f * x;
    return fmaf(hx, t, hx);
}

// ---------------------------------------------------------------------------
// aux: blocks 0..63 build Wt (tf32-rna transpose of W1 rows 0..127);
//      block 64 detects batch dtype (word [C-1] is 0 iff int64).
// ---------------------------------------------------------------------------
__global__ void __launch_bounds__(256) aux_kernel(const float* __restrict__ W1,
                                                  const int* __restrict__ batch_words,
                                                  int C) {
    if (blockIdx.x == 64) {
        if (threadIdx.x == 0) g_is64 = (batch_words[C - 1] == 0) ? 1 : 0;
        return;
    }
    const int idx = blockIdx.x * 256 + threadIdx.x;   // 16384
    const int n = idx >> 7, k = idx & 127;
    g_Wt[n * 128 + k] = __uint_as_float(f2tf32(W1[k * Dv + n]));
}

// base[b][d] = b1[d] + z_local[b]·W1[128:256] + z_meta·W1[256:384]
__global__ void __launch_bounds__(128) prep_kernel(
    const float* __restrict__ z_local, const float* __restrict__ z_meta,
    const float* __restrict__ W1, const float* __restrict__ b1)
{
    extern __shared__ float smem_f[];
    float* Wp  = smem_f;
    float* zsh = smem_f + 256 * Dv;
    const int tid = threadIdx.x;

    const float4* Wsrc = (const float4*)(W1 + Dv * Dv);
    float4* Wdst = (float4*)Wp;
    for (int i = tid; i < 256 * Dv / 4; i += 128) Wdst[i] = Wsrc[i];
    zsh[Dv + tid] = z_meta[tid];
    __syncthreads();

    const int b0 = blockIdx.x * 32;
    for (int g = 0; g < 32; ++g) {
        const int b = b0 + g;
        zsh[tid] = z_local[b * Dv + tid];
        __syncthreads();
        float acc = b1[tid];
        #pragma unroll 8
        for (int k = 0; k < 256; ++k)
            acc = fmaf(zsh[k], Wp[k * Dv + tid], acc);
        g_base[b * Dv + tid] = acc;
        __syncthreads();
    }
}

// ---------------------------------------------------------------------------
// Persistent main kernel, cross-tile software pipelined: the epilogue of tile
// i-1 (GELU/MUFU + base LDG + w2 FMA) is interleaved into tile i's MMA loop,
// so tensor, MUFU and L2 pipes run concurrently instead of phase-serial.
// ---------------------------------------------------------------------------
__global__ void __launch_bounds__(256, 1) main_kernel(
    const float* __restrict__ nodes,
    const float* __restrict__ W2,
    const float* __restrict__ b2,
    const void*  __restrict__ batch,
    float* __restrict__ out, int C, int T)
{
    extern __shared__ float smem_f[];
    const uint32_t smem_base = smem_u32(smem_f);
    float* w2sh = smem_f + W2_OFF;
    float* red  = smem_f + RED_OFF;

    const int tid  = threadIdx.x;
    const int lane = tid & 31;
    const int warp = tid >> 5;
    const int wm   = warp >> 1;          // 0..3: rows wm*32
    const int wn   = warp & 1;           // 0..1: cols wn*64

    // ---- one-time Wt stage: rows n, pitch 132 ----
    {
        const float4* src = (const float4*)g_Wt;
        for (int idx = tid; idx < 4096; idx += 256) {
            const int r = idx >> 5, c = idx & 31;
            *(float4*)(smem_f + WT_OFF + r * A_PITCH + c * 4) = src[idx];
        }
        if (tid < 128) w2sh[tid] = W2[tid];
    }
    const float b2v  = b2[0];
    const int   is64 = g_is64;
    const int*       bt32 = (const int*)batch;
    const long long* bt64 = (const long long*)batch;

    // ---- ldmatrix lane addresses (verified R6) ----
    const int rowA = wm * 32 + ((lane >> 3) & 1) * 8 + (lane & 7);
    const uint32_t aoffA = (uint32_t)(rowA * A_PITCH) * 4 + (lane >> 4) * 16;
    const int nB = wn * 64 + ((lane >> 4) & 1) * 8 + (lane & 7);
    uint32_t bAdr[4];
    #pragma unroll
    for (int p = 0; p < 4; ++p)
        bAdr[p] = smem_base + (uint32_t)(WT_OFF + (nB + p * 16) * A_PITCH) * 4
                + ((lane >> 3) & 1) * 16;

    auto issueA = [&](int bufW, int t) {
        const int g0 = t * 128;
        int nr = C - g0; if (nr > 128) nr = 128;
        const char* src0 = (const char*)(nodes + (size_t)g0 * Dv);
        #pragma unroll
        for (int j = 0; j < 16; ++j) {
            const int e = j * 256 + tid;
            const int r = e >> 5, c = e & 31;
            if (r < nr) {
                const uint32_t dst = smem_base + (uint32_t)(bufW + r * A_PITCH + c * 4) * 4;
                CP_ASYNC16(dst, src0 + (size_t)r * 512 + c * 16);
            }
        }
    };
    auto loadBidx = [&](int gr0, int bidx[2][2]) {
        #pragma unroll
        for (int tm = 0; tm < 2; ++tm)
            #pragma unroll
            for (int rh = 0; rh < 2; ++rh) {
                const int gr = gr0 + wm * 32 + tm * 16 + rh * 8 + (lane >> 2);
                bidx[tm][rh] = (gr < C) ? (is64 ? (int)bt64[gr] : bt32[gr]) : 0;
            }
    };
    // finish reduction + out-write for tile with origin pgr0 (pp = 4 partials)
    auto finishEpi = [&](int pgr0, float pp[4]) {
        #pragma unroll
        for (int tm = 0; tm < 2; ++tm)
            #pragma unroll
            for (int rh = 0; rh < 2; ++rh) {
                float partial = pp[tm * 2 + rh];
                partial += __shfl_xor_sync(0xFFFFFFFFu, partial, 1);
                partial += __shfl_xor_sync(0xFFFFFFFFu, partial, 2);
                const int row = wm * 32 + tm * 16 + rh * 8 + (lane >> 2);
                if ((lane & 3) == 0) red[row * 2 + wn] = partial;
            }
        __syncthreads();
        if (tid < 128) {
            const int g2 = pgr0 + tid;
            if (g2 < C) out[g2] = red[tid * 2] + red[tid * 2 + 1] + b2v;
        }
    };

    float accN[2][8][4], accO[2][8][4];
    int   pbidx[2][2];
    int   pgr0 = 0;
    const int n0base = wn * 64 + (lane & 3) * 2;

    int tile = blockIdx.x;
    int p = 0;
    issueA(A0_OFF, tile);
    CP_COMMIT();

    // ---- prologue: first tile mainloop (no old epilogue) ----
    {
        CP_WAIT0();
        __syncthreads();
        const int nxt = tile + gridDim.x;
        if (nxt < T) issueA(A1_OFF, nxt);
        CP_COMMIT();

        #pragma unroll
        for (int t = 0; t < 2; ++t)
            #pragma unroll
            for (int n = 0; n < 8; ++n)
                #pragma unroll
                for (int i = 0; i < 4; ++i) accN[t][n][i] = 0.f;

        const uint32_t aBase = smem_base + (uint32_t)A0_OFF * 4 + aoffA;
        #pragma unroll
        for (int ks = 0; ks < 16; ++ks) {
            uint32_t a0[4], a1[4], bf[4][4];
            LDSM_X4(a0[0], a0[1], a0[2], a0[3], aBase + ks * 32);
            LDSM_X4(a1[0], a1[1], a1[2], a1[3], aBase + ks * 32 + 16 * A_PITCH * 4);
            #pragma unroll
            for (int q = 0; q < 4; ++q)
                LDSM_X4(bf[q][0], bf[q][1], bf[q][2], bf[q][3], bAdr[q] + ks * 32);
            #pragma unroll
            for (int q = 0; q < 4; ++q) {
                MMA_TF32(accN[0][2 * q + 0], a0, bf[q][0], bf[q][1]);
                MMA_TF32(accN[1][2 * q + 0], a1, bf[q][0], bf[q][1]);
                MMA_TF32(accN[0][2 * q + 1], a0, bf[q][2], bf[q][3]);
                MMA_TF32(accN[1][2 * q + 1], a1, bf[q][2], bf[q][3]);
            }
        }
        #pragma unroll
        for (int t = 0; t < 2; ++t)
            #pragma unroll
            for (int n = 0; n < 8; ++n)
                #pragma unroll
                for (int i = 0; i < 4; ++i) accO[t][n][i] = accN[t][n][i];
        loadBidx(tile * 128, pbidx);
        pgr0 = tile * 128;
        tile += gridDim.x;
        p = 1;
    }

    // ---- steady state: mainloop(tile) fused with epilogue(tile-grid) ----
    for (; tile < T; tile += gridDim.x) {
        CP_WAIT0();
        __syncthreads();
        const int nxt = tile + gridDim.x;
        if (nxt < T) issueA(p ? A0_OFF : A1_OFF, nxt);
        CP_COMMIT();

        int bidx[2][2];
        loadBidx(tile * 128, bidx);

        #pragma unroll
        for (int t = 0; t < 2; ++t)
            #pragma unroll
            for (int n = 0; n < 8; ++n)
                #pragma unroll
                for (int i = 0; i < 4; ++i) accN[t][n][i] = 0.f;

        float pp[4] = {0.f, 0.f, 0.f, 0.f};
        const uint32_t aBase = smem_base + (uint32_t)(p ? A1_OFF : A0_OFF) * 4 + aoffA;

        #pragma unroll
        for (int ks = 0; ks < 16; ++ks) {
            uint32_t a0[4], a1[4], bf[4][4];
            LDSM_X4(a0[0], a0[1], a0[2], a0[3], aBase + ks * 32);
            LDSM_X4(a1[0], a1[1], a1[2], a1[3], aBase + ks * 32 + 16 * A_PITCH * 4);
            #pragma unroll
            for (int q = 0; q < 4; ++q)
                LDSM_X4(bf[q][0], bf[q][1], bf[q][2], bf[q][3], bAdr[q] + ks * 32);

            // epilogue chunk of previous tile: (tm, nt) = (ks>>3, ks&7)
            {
                const int tm = ks >> 3, nt = ks & 7;
                const int n0 = n0base + nt * 8;
                const float2 w2v = *(const float2*)(w2sh + n0);
                const float2 bv0 = __ldg((const float2*)(g_base + pbidx[tm][0] * Dv + n0));
                const float2 bv1 = __ldg((const float2*)(g_base + pbidx[tm][1] * Dv + n0));
                const float x0 = accO[tm][nt][0] + bv0.x;
                const float x1 = accO[tm][nt][1] + bv0.y;
                const float x2 = accO[tm][nt][2] + bv1.x;
                const float x3 = accO[tm][nt][3] + bv1.y;
                pp[tm * 2 + 0] = fmaf(gelu_fast(x0), w2v.x, pp[tm * 2 + 0]);
                pp[tm * 2 + 0] = fmaf(gelu_fast(x1), w2v.y, pp[tm * 2 + 0]);
                pp[tm * 2 + 1] = fmaf(gelu_fast(x2), w2v.x, pp[tm * 2 + 1]);
                pp[tm * 2 + 1] = fmaf(gelu_fast(x3), w2v.y, pp[tm * 2 + 1]);
            }

            #pragma unroll
            for (int q = 0; q < 4; ++q) {
                MMA_TF32(accN[0][2 * q + 0], a0, bf[q][0], bf[q][1]);
                MMA_TF32(accN[1][2 * q + 0], a1, bf[q][0], bf[q][1]);
                MMA_TF32(accN[0][2 * q + 1], a0, bf[q][2], bf[q][3]);
                MMA_TF32(accN[1][2 * q + 1], a1, bf[q][2], bf[q][3]);
            }
        }

        finishEpi(pgr0, pp);

        #pragma unroll
        for (int t = 0; t < 2; ++t)
            #pragma unroll
            for (int n = 0; n < 8; ++n)
                #pragma unroll
                for (int i = 0; i < 4; ++i) accO[t][n][i] = accN[t][n][i];
        pbidx[0][0] = bidx[0][0]; pbidx[0][1] = bidx[0][1];
        pbidx[1][0] = bidx[1][0]; pbidx[1][1] = bidx[1][1];
        pgr0 = tile * 128;
        p ^= 1;
    }

    // ---- drain: standalone epilogue for the last tile ----
    {
        float pp[4] = {0.f, 0.f, 0.f, 0.f};
        #pragma unroll
        for (int ks = 0; ks < 16; ++ks) {
            const int tm = ks >> 3, nt = ks & 7;
            const int n0 = n0base + nt * 8;
            const float2 w2v = *(const float2*)(w2sh + n0);
            const float2 bv0 = __ldg((const float2*)(g_base + pbidx[tm][0] * Dv + n0));
            const float2 bv1 = __ldg((const float2*)(g_base + pbidx[tm][1] * Dv + n0));
            const float x0 = accO[tm][nt][0] + bv0.x;
            const float x1 = accO[tm][nt][1] + bv0.y;
            const float x2 = accO[tm][nt][2] + bv1.x;
            const float x3 = accO[tm][nt][3] + bv1.y;
            pp[tm * 2 + 0] = fmaf(gelu_fast(x0), w2v.x, pp[tm * 2 + 0]);
            pp[tm * 2 + 0] = fmaf(gelu_fast(x1), w2v.y, pp[tm * 2 + 0]);
            pp[tm * 2 + 1] = fmaf(gelu_fast(x2), w2v.x, pp[tm * 2 + 1]);
            pp[tm * 2 + 1] = fmaf(gelu_fast(x3), w2v.y, pp[tm * 2 + 1]);
        }
        __syncthreads();     // red buffer may still be read by out-write above
        finishEpi(pgr0, pp);
    }
}

// ---------------------------------------------------------------------------
extern "C" void kernel_launch(void* const* d_in, const int* in_sizes, int n_in,
                              void* d_out, int out_size)
{
    const float* nodes   = (const float*)d_in[0];
    const float* z_local = (const float*)d_in[1];
    const float* z_meta  = (const float*)d_in[2];
    const float* W1      = (const float*)d_in[3];
    const float* b1      = (const float*)d_in[4];
    const float* W2      = (const float*)d_in[5];
    const float* b2      = (const float*)d_in[6];
    const void*  batch   = d_in[7];
    float* out = (float*)d_out;

    const int C = in_sizes[7];
    const int B = in_sizes[1] / Dv;
    const int T = (C + 127) / 128;

    int dev = 0, nsm = 148;
    cudaGetDevice(&dev);
    cudaDeviceGetAttribute(&nsm, cudaDevAttrMultiProcessorCount, dev);

    const int PREP_SMEM = (256 * Dv + 256) * (int)sizeof(float);   // 132096
    const int MAIN_SMEM = SMEM_WORDS * (int)sizeof(float);         // 204288

    cudaFuncSetAttribute(prep_kernel, cudaFuncAttributeMaxDynamicSharedMemorySize, PREP_SMEM);
    cudaFuncSetAttribute(main_kernel, cudaFuncAttributeMaxDynamicSharedMemorySize, MAIN_SMEM);

    aux_kernel<<<65, 256>>>(W1, (const int*)batch, C);
    prep_kernel<<<B / 32, 128, PREP_SMEM>>>(z_local, z_meta, W1, b1);

    main_kernel<<<nsm, 256, MAIN_SMEM>>>(nodes, W2, b2, batch, out, C, T);
}

// round 10
// speedup vs baseline: 5.0370x; 1.0767x over previous
#include <cuda_runtime.h>
#include <cuda_fp16.h>
#include <math.h>
#include <stdint.h>

#define Dv   128
#define Bv   4096

// SMEM word layout (main kernel)
#define S0_OFF  0         // fp32 stage buf 0: 128x128 (cp.async target)
#define S1_OFF  16384     // fp32 stage buf 1
#define AH_OFF  32768     // fp16 A tile: 128 rows x 136 halves (pitch 272B) = 8704 words
#define WH_OFF  41472     // fp16 Wt tile: same shape
#define W2_OFF  50176     // 128 words
#define RED_OFF 50304     // 128 rows x 4 partials
#define SMEM_WORDS 50816  // 203264 B

// Scratch globals
__device__ float g_base[Bv * Dv];                 // per-graph base rows (2 MB)
__device__ __align__(16) __half g_Wh[128 * 136];  // W1a^T fp16, pitch 136 halves
__device__ int   g_is64;

// ---------------- helpers ----------------
__device__ __forceinline__ uint32_t smem_u32(const void* p) {
    uint32_t a;
    asm("{ .reg .u64 t; cvta.to.shared.u64 t, %1; cvt.u32.u64 %0, t; }" : "=r"(a) : "l"(p));
    return a;
}
__device__ __forceinline__ uint32_t pack_h2(float lo, float hi) {
    uint32_t r;
    asm("cvt.rn.f16x2.f32 %0, %1, %2;" : "=r"(r) : "f"(hi), "f"(lo));
    return r;
}
#define CP_ASYNC16(dst, src) \
    asm volatile("cp.async.cg.shared.global [%0], [%1], 16;" :: "r"(dst), "l"(src) : "memory")
#define CP_COMMIT() asm volatile("cp.async.commit_group;" ::: "memory")
#define CP_WAIT0()  asm volatile("cp.async.wait_group 0;" ::: "memory")

#define LDSM_X4(r0, r1, r2, r3, addr)                                          \
    asm volatile("ldmatrix.sync.aligned.m8n8.x4.shared.b16 {%0,%1,%2,%3}, [%4];" \
        : "=r"(r0), "=r"(r1), "=r"(r2), "=r"(r3) : "r"(addr))

// mma.sync m16n8k16 fp16 -> fp32 accum
#define MMA_F16(c, a, b0_, b1_)                                                \
    asm volatile(                                                              \
        "mma.sync.aligned.m16n8k16.row.col.f32.f16.f16.f32 "                   \
        "{%0,%1,%2,%3}, {%4,%5,%6,%7}, {%8,%9}, {%0,%1,%2,%3};"                \
        : "+f"((c)[0]), "+f"((c)[1]), "+f"((c)[2]), "+f"((c)[3])               \
        : "r"((a)[0]), "r"((a)[1]), "r"((a)[2]), "r"((a)[3]),                  \
          "r"(b0_), "r"(b1_))

// gelu(x) = 0.5x(1+tanh(0.79788456x + 0.03567741x^3)) -- single MUFU tanh
__device__ __forceinline__ float gelu_fast(float x) {
    const float z = x * fmaf(0.035677408f, x * x, 0.7978845608f);
    float t;
    asm("tanh.approx.f32 %0, %1;" : "=f"(t) : "f"(z));
    const float hx = 0.5f * x;
    return fmaf(hx, t, hx);
}

// ---------------------------------------------------------------------------
// aux: blocks 0..63 build g_Wh = fp16(W1a^T) at pitch 136;
//      block 64 detects batch dtype (word [C-1] is 0 iff int64).
// ---------------------------------------------------------------------------
__global__ void __launch_bounds__(256) aux_kernel(const float* __restrict__ W1,
                                                  const int* __restrict__ batch_words,
                                                  int C) {
    if (blockIdx.x == 64) {
        if (threadIdx.x == 0) g_is64 = (batch_words[C - 1] == 0) ? 1 : 0;
        return;
    }
    const int idx = blockIdx.x * 256 + threadIdx.x;   // 16384
    const int n = idx >> 7, k = idx & 127;
    g_Wh[n * 136 + k] = __float2half_rn(W1[k * Dv + n]);
}

// base[b][d] = b1[d] + z_local[b]·W1[128:256] + z_meta·W1[256:384]
__global__ void __launch_bounds__(128) prep_kernel(
    const float* __restrict__ z_local, const float* __restrict__ z_meta,
    const float* __restrict__ W1, const float* __restrict__ b1)
{
    extern __shared__ float smem_f[];
    float* Wp  = smem_f;
    float* zsh = smem_f + 256 * Dv;
    const int tid = threadIdx.x;

    const float4* Wsrc = (const float4*)(W1 + Dv * Dv);
    float4* Wdst = (float4*)Wp;
    for (int i = tid; i < 256 * Dv / 4; i += 128) Wdst[i] = Wsrc[i];
    zsh[Dv + tid] = z_meta[tid];
    __syncthreads();

    const int b0 = blockIdx.x * 32;
    for (int g = 0; g < 32; ++g) {
        const int b = b0 + g;
        zsh[tid] = z_local[b * Dv + tid];
        __syncthreads();
        float acc = b1[tid];
        #pragma unroll 8
        for (int k = 0; k < 256; ++k)
            acc = fmaf(zsh[k], Wp[k * Dv + tid], acc);
        g_base[b * Dv + tid] = acc;
        __syncthreads();
    }
}

// ---------------------------------------------------------------------------
// Persistent main kernel, 512 threads (16 warps, warp tile 32M x 32N), fp16
// m16n8k16 MMA, cp.async fp32 double-buffer + SMEM cvt pass, cross-tile
// epilogue pipelining (epilogue of tile i-1 interleaved into tile i's MMAs).
// ---------------------------------------------------------------------------
__global__ void __launch_bounds__(512, 1) main_kernel(
    const float* __restrict__ nodes,
    const float* __restrict__ W2,
    const float* __restrict__ b2,
    const void*  __restrict__ batch,
    float* __restrict__ out, int C, int T)
{
    extern __shared__ float smem_f[];
    const uint32_t smem_base = smem_u32(smem_f);
    float* w2sh = smem_f + W2_OFF;
    float* red  = smem_f + RED_OFF;

    const int tid  = threadIdx.x;
    const int lane = tid & 31;
    const int warp = tid >> 5;
    const int wm   = warp >> 2;          // 0..3: rows wm*32
    const int wn   = warp & 3;           // 0..3: cols wn*32

    // ---- one-time Wh stage (full 34816 B = 2176 float4) ----
    {
        const float4* src = (const float4*)g_Wh;     // 2176 float4
        float4* dst = (float4*)(smem_f + WH_OFF);
        for (int idx = tid; idx < 2176; idx += 512) dst[idx] = src[idx];
        if (tid < 128) w2sh[tid] = W2[tid];
    }
    const float b2v  = b2[0];
    const int   is64 = g_is64;
    const int*       bt32 = (const int*)batch;
    const long long* bt64 = (const long long*)batch;

    // ---- ldmatrix lane addresses (fp16, pitch 272B) ----
    // A: mats (rows 0-7,kLo)(rows 8-15,kLo)(rows 0-7,kHi)(rows 8-15,kHi)
    const int rowA = wm * 32 + (lane & 7) + ((lane >> 3) & 1) * 8;
    const uint32_t aA = smem_base + AH_OFF * 4 + (uint32_t)rowA * 272
                      + ((lane >> 4) & 1) * 16;
    // B pair p: mats (n..n+7,kLo)(n..n+7,kHi)(n+8..15,kLo)(n+8..15,kHi)
    uint32_t bAdr[2];
    #pragma unroll
    for (int p = 0; p < 2; ++p) {
        const int nB = wn * 32 + p * 16 + (lane & 7) + ((lane >> 4) & 1) * 8;
        bAdr[p] = smem_base + WH_OFF * 4 + (uint32_t)nB * 272
                + ((lane >> 3) & 1) * 16;
    }

    auto issueA = [&](int bufW, int t) {
        const int g0 = t * 128;
        int nr = C - g0; if (nr > 128) nr = 128;
        const char* src0 = (const char*)(nodes + (size_t)g0 * Dv);
        #pragma unroll
        for (int j = 0; j < 8; ++j) {
            const int e = j * 512 + tid;
            const int r = e >> 5, c = e & 31;
            if (r < nr) {
                const uint32_t dst = smem_base + (uint32_t)(bufW + r * 128 + c * 4) * 4;
                CP_ASYNC16(dst, src0 + (size_t)r * 512 + c * 16);
            }
        }
    };
    // cvt pass: fp32 stage buffer -> fp16 A tile (pitch 136 halves)
    auto cvtA = [&](int bufW) {
        const float4* S = (const float4*)(smem_f + bufW);
        #pragma unroll
        for (int j = 0; j < 8; ++j) {
            const int fi = j * 512 + tid;           // 0..4095
            const int r = fi >> 5, c4 = fi & 31;
            const float4 v = S[fi];
            uint2 hh;
            hh.x = pack_h2(v.x, v.y);
            hh.y = pack_h2(v.z, v.w);
            *(uint2*)((char*)smem_f + AH_OFF * 4 + r * 272 + c4 * 8) = hh;
        }
    };
    auto loadBidx = [&](int gr0, int bidx[2][2]) {
        #pragma unroll
        for (int tm = 0; tm < 2; ++tm)
            #pragma unroll
            for (int rh = 0; rh < 2; ++rh) {
                const int gr = gr0 + wm * 32 + tm * 16 + rh * 8 + (lane >> 2);
                bidx[tm][rh] = (gr < C) ? (is64 ? (int)bt64[gr] : bt32[gr]) : 0;
            }
    };
    auto finishEpi = [&](int pgr0, float pp[4]) {
        #pragma unroll
        for (int tm = 0; tm < 2; ++tm)
            #pragma unroll
            for (int rh = 0; rh < 2; ++rh) {
                float partial = pp[tm * 2 + rh];
                partial += __shfl_xor_sync(0xFFFFFFFFu, partial, 1);
                partial += __shfl_xor_sync(0xFFFFFFFFu, partial, 2);
                const int row = wm * 32 + tm * 16 + rh * 8 + (lane >> 2);
                if ((lane & 3) == 0) red[row * 4 + wn] = partial;
            }
        __syncthreads();
        if (tid < 128) {
            const int g2 = pgr0 + tid;
            if (g2 < C) out[g2] = red[tid * 4] + red[tid * 4 + 1]
                                + red[tid * 4 + 2] + red[tid * 4 + 3] + b2v;
        }
    };

    float accN[8][4], accO[8][4];    // [tm*4+nt][c]
    int   pbidx[2][2];
    int   pgr0 = 0;
    const int n0base = wn * 32 + (lane & 3) * 2;

    int tile = blockIdx.x;
    int p = 0;                       // current fp32 stage buffer parity
    issueA(S0_OFF, tile);
    CP_COMMIT();

    // ---- prologue: first tile (no old epilogue) ----
    {
        CP_WAIT0();
        __syncthreads();
        const int nxt = tile + gridDim.x;
        if (nxt < T) issueA(S1_OFF, nxt);
        CP_COMMIT();
        cvtA(S0_OFF);
        __syncthreads();

        #pragma unroll
        for (int n = 0; n < 8; ++n)
            #pragma unroll
            for (int i = 0; i < 4; ++i) accN[n][i] = 0.f;

        #pragma unroll
        for (int ks = 0; ks < 8; ++ks) {
            uint32_t a0[4], a1[4], u0[4], u1[4];
            LDSM_X4(a0[0], a0[1], a0[2], a0[3], aA + ks * 32);
            LDSM_X4(a1[0], a1[1], a1[2], a1[3], aA + ks * 32 + 16 * 272);
            LDSM_X4(u0[0], u0[1], u0[2], u0[3], bAdr[0] + ks * 32);
            LDSM_X4(u1[0], u1[1], u1[2], u1[3], bAdr[1] + ks * 32);
            MMA_F16(accN[0], a0, u0[0], u0[1]);
            MMA_F16(accN[1], a0, u0[2], u0[3]);
            MMA_F16(accN[2], a0, u1[0], u1[1]);
            MMA_F16(accN[3], a0, u1[2], u1[3]);
            MMA_F16(accN[4], a1, u0[0], u0[1]);
            MMA_F16(accN[5], a1, u0[2], u0[3]);
            MMA_F16(accN[6], a1, u1[0], u1[1]);
            MMA_F16(accN[7], a1, u1[2], u1[3]);
        }
        #pragma unroll
        for (int n = 0; n < 8; ++n)
            #pragma unroll
            for (int i = 0; i < 4; ++i) accO[n][i] = accN[n][i];
        loadBidx(tile * 128, pbidx);
        pgr0 = tile * 128;
        tile += gridDim.x;
        p = 1;
    }

    // ---- steady state ----
    for (; tile < T; tile += gridDim.x) {
        CP_WAIT0();
        __syncthreads();
        const int nxt = tile + gridDim.x;
        if (nxt < T) issueA(p ? S0_OFF : S1_OFF, nxt);
        CP_COMMIT();
        cvtA(p ? S1_OFF : S0_OFF);
        __syncthreads();

        int bidx[2][2];
        loadBidx(tile * 128, bidx);

        #pragma unroll
        for (int n = 0; n < 8; ++n)
            #pragma unroll
            for (int i = 0; i < 4; ++i) accN[n][i] = 0.f;

        float pp[4] = {0.f, 0.f, 0.f, 0.f};

        #pragma unroll
        for (int ks = 0; ks < 8; ++ks) {
            uint32_t a0[4], a1[4], u0[4], u1[4];
            LDSM_X4(a0[0], a0[1], a0[2], a0[3], aA + ks * 32);
            LDSM_X4(a1[0], a1[1], a1[2], a1[3], aA + ks * 32 + 16 * 272);
            LDSM_X4(u0[0], u0[1], u0[2], u0[3], bAdr[0] + ks * 32);
            LDSM_X4(u1[0], u1[1], u1[2], u1[3], bAdr[1] + ks * 32);

            // epilogue chunk of previous tile: tm = ks>>2, nt = ks&3
            {
                const int tm = ks >> 2, nt = ks & 3;
                const int n0 = n0base + nt * 8;
                const float2 w2v = *(const float2*)(w2sh + n0);
                const float2 bv0 = __ldg((const float2*)(g_base + pbidx[tm][0] * Dv + n0));
                const float2 bv1 = __ldg((const float2*)(g_base + pbidx[tm][1] * Dv + n0));
                const float x0 = accO[tm * 4 + nt][0] + bv0.x;
                const float x1 = accO[tm * 4 + nt][1] + bv0.y;
                const float x2 = accO[tm * 4 + nt][2] + bv1.x;
                const float x3 = accO[tm * 4 + nt][3] + bv1.y;
                pp[tm * 2 + 0] = fmaf(gelu_fast(x0), w2v.x, pp[tm * 2 + 0]);
                pp[tm * 2 + 0] = fmaf(gelu_fast(x1), w2v.y, pp[tm * 2 + 0]);
                pp[tm * 2 + 1] = fmaf(gelu_fast(x2), w2v.x, pp[tm * 2 + 1]);
                pp[tm * 2 + 1] = fmaf(gelu_fast(x3), w2v.y, pp[tm * 2 + 1]);
            }

            MMA_F16(accN[0], a0, u0[0], u0[1]);
            MMA_F16(accN[1], a0, u0[2], u0[3]);
            MMA_F16(accN[2], a0, u1[0], u1[1]);
            MMA_F16(accN[3], a0, u1[2], u1[3]);
            MMA_F16(accN[4], a1, u0[0], u0[1]);
            MMA_F16(accN[5], a1, u0[2], u0[3]);
            MMA_F16(accN[6], a1, u1[0], u1[1]);
            MMA_F16(accN[7], a1, u1[2], u1[3]);
        }

        finishEpi(pgr0, pp);

        #pragma unroll
        for (int n = 0; n < 8; ++n)
            #pragma unroll
            for (int i = 0; i < 4; ++i) accO[n][i] = accN[n][i];
        pbidx[0][0] = bidx[0][0]; pbidx[0][1] = bidx[0][1];
        pbidx[1][0] = bidx[1][0]; pbidx[1][1] = bidx[1][1];
        pgr0 = tile * 128;
        p ^= 1;
    }

    // ---- drain: standalone epilogue for the last tile ----
    {
        float pp[4] = {0.f, 0.f, 0.f, 0.f};
        #pragma unroll
        for (int ks = 0; ks < 8; ++ks) {
            const int tm = ks >> 2, nt = ks & 3;
            const int n0 = n0base + nt * 8;
            const float2 w2v = *(const float2*)(w2sh + n0);
            const float2 bv0 = __ldg((const float2*)(g_base + pbidx[tm][0] * Dv + n0));
            const float2 bv1 = __ldg((const float2*)(g_base + pbidx[tm][1] * Dv + n0));
            const float x0 = accO[tm * 4 + nt][0] + bv0.x;
            const float x1 = accO[tm * 4 + nt][1] + bv0.y;
            const float x2 = accO[tm * 4 + nt][2] + bv1.x;
            const float x3 = accO[tm * 4 + nt][3] + bv1.y;
            pp[tm * 2 + 0] = fmaf(gelu_fast(x0), w2v.x, pp[tm * 2 + 0]);
            pp[tm * 2 + 0] = fmaf(gelu_fast(x1), w2v.y, pp[tm * 2 + 0]);
            pp[tm * 2 + 1] = fmaf(gelu_fast(x2), w2v.x, pp[tm * 2 + 1]);
            pp[tm * 2 + 1] = fmaf(gelu_fast(x3), w2v.y, pp[tm * 2 + 1]);
        }
        __syncthreads();
        finishEpi(pgr0, pp);
    }
}

// ---------------------------------------------------------------------------
extern "C" void kernel_launch(void* const* d_in, const int* in_sizes, int n_in,
                              void* d_out, int out_size)
{
    const float* nodes   = (const float*)d_in[0];
    const float* z_local = (const float*)d_in[1];
    const float* z_meta  = (const float*)d_in[2];
    const float* W1      = (const float*)d_in[3];
    const float* b1      = (const float*)d_in[4];
    const float* W2      = (const float*)d_in[5];
    const float* b2      = (const float*)d_in[6];
    const void*  batch   = d_in[7];
    float* out = (float*)d_out;

    const int C = in_sizes[7];
    const int B = in_sizes[1] / Dv;
    const int T = (C + 127) / 128;

    int dev = 0, nsm = 148;
    cudaGetDevice(&dev);
    cudaDeviceGetAttribute(&nsm, cudaDevAttrMultiProcessorCount, dev);

    const int PREP_SMEM = (256 * Dv + 256) * (int)sizeof(float);   // 132096
    const int MAIN_SMEM = SMEM_WORDS * (int)sizeof(float);         // 203264

    cudaFuncSetAttribute(prep_kernel, cudaFuncAttributeMaxDynamicSharedMemorySize, PREP_SMEM);
    cudaFuncSetAttribute(main_kernel, cudaFuncAttributeMaxDynamicSharedMemorySize, MAIN_SMEM);

    aux_kernel<<<65, 256>>>(W1, (const int*)batch, C);
    prep_kernel<<<B / 32, 128, PREP_SMEM>>>(z_local, z_meta, W1, b1);

    main_kernel<<<nsm, 512, MAIN_SMEM>>>(nodes, W2, b2, batch, out, C, T);
}

// round 11
// speedup vs baseline: 5.1702x; 1.0264x over previous
#include <cuda_runtime.h>
#include <cuda_fp16.h>
#include <math.h>
#include <stdint.h>

#define Dv   128
#define Bv   4096

// SMEM word layout (main kernel)
#define S_OFF     0                       // fp32 stage: 128x128 (cp.async target)
#define AH0_OFF   16384                   // fp16 A tile 0: 128 x 136 halves (272B pitch)
#define AH_STRIDE 8704                    // words per AH buffer (34816 B)
#define AH1_OFF   (AH0_OFF + AH_STRIDE)   // 25088
#define WH_OFF    (AH1_OFF + AH_STRIDE)   // 33792
#define W2_OFF    (WH_OFF + AH_STRIDE)    // 42496
#define RED_OFF   (W2_OFF + 128)          // 42624
#define SMEM_WORDS (RED_OFF + 512)        // 43136 -> 172544 B

// Scratch globals
__device__ float g_base[Bv * Dv];                 // per-graph base rows (2 MB)
__device__ __align__(16) __half g_Wh[128 * 136];  // W1a^T fp16, pitch 136 halves
__device__ int   g_is64;

// ---------------- helpers ----------------
__device__ __forceinline__ uint32_t smem_u32(const void* p) {
    uint32_t a;
    asm("{ .reg .u64 t; cvta.to.shared.u64 t, %1; cvt.u32.u64 %0, t; }" : "=r"(a) : "l"(p));
    return a;
}
__device__ __forceinline__ uint32_t pack_h2(float lo, float hi) {
    uint32_t r;
    asm("cvt.rn.f16x2.f32 %0, %1, %2;" : "=r"(r) : "f"(hi), "f"(lo));
    return r;
}
#define CP_ASYNC16(dst, src) \
    asm volatile("cp.async.cg.shared.global [%0], [%1], 16;" :: "r"(dst), "l"(src) : "memory")
#define CP_COMMIT() asm volatile("cp.async.commit_group;" ::: "memory")
#define CP_WAIT0()  asm volatile("cp.async.wait_group 0;" ::: "memory")

#define LDSM_X4(r0, r1, r2, r3, addr)                                          \
    asm volatile("ldmatrix.sync.aligned.m8n8.x4.shared.b16 {%0,%1,%2,%3}, [%4];" \
        : "=r"(r0), "=r"(r1), "=r"(r2), "=r"(r3) : "r"(addr))

// mma.sync m16n8k16 fp16 -> fp32 accum
#define MMA_F16(c, a, b0_, b1_)                                                \
    asm volatile(                                                              \
        "mma.sync.aligned.m16n8k16.row.col.f32.f16.f16.f32 "                   \
        "{%0,%1,%2,%3}, {%4,%5,%6,%7}, {%8,%9}, {%0,%1,%2,%3};"                \
        : "+f"((c)[0]), "+f"((c)[1]), "+f"((c)[2]), "+f"((c)[3])               \
        : "r"((a)[0]), "r"((a)[1]), "r"((a)[2]), "r"((a)[3]),                  \
          "r"(b0_), "r"(b1_))

// gelu(x) = 0.5x(1+tanh(0.79788456x + 0.03567741x^3)) -- single MUFU tanh
__device__ __forceinline__ float gelu_fast(float x) {
    const float z = x * fmaf(0.035677408f, x * x, 0.7978845608f);
    float t;
    asm("tanh.approx.f32 %0, %1;" : "=f"(t) : "f"(z));
    const float hx = 0.5f * x;
    return fmaf(hx, t, hx);
}

// ---------------------------------------------------------------------------
// aux: blocks 0..63 build g_Wh = fp16(W1a^T) at pitch 136;
//      block 64 detects batch dtype (word [C-1] is 0 iff int64).
// ---------------------------------------------------------------------------
__global__ void __launch_bounds__(256) aux_kernel(const float* __restrict__ W1,
                                                  const int* __restrict__ batch_words,
                                                  int C) {
    if (blockIdx.x == 64) {
        if (threadIdx.x == 0) g_is64 = (batch_words[C - 1] == 0) ? 1 : 0;
        return;
    }
    const int idx = blockIdx.x * 256 + threadIdx.x;   // 16384
    const int n = idx >> 7, k = idx & 127;
    g_Wh[n * 136 + k] = __float2half_rn(W1[k * Dv + n]);
}

// base[b][d] = b1[d] + z_local[b]·W1[128:256] + z_meta·W1[256:384]
__global__ void __launch_bounds__(128) prep_kernel(
    const float* __restrict__ z_local, const float* __restrict__ z_meta,
    const float* __restrict__ W1, const float* __restrict__ b1)
{
    extern __shared__ float smem_f[];
    float* Wp  = smem_f;
    float* zsh = smem_f + 256 * Dv;
    const int tid = threadIdx.x;

    const float4* Wsrc = (const float4*)(W1 + Dv * Dv);
    float4* Wdst = (float4*)Wp;
    for (int i = tid; i < 256 * Dv / 4; i += 128) Wdst[i] = Wsrc[i];
    zsh[Dv + tid] = z_meta[tid];
    __syncthreads();

    const int b0 = blockIdx.x * 32;
    for (int g = 0; g < 32; ++g) {
        const int b = b0 + g;
        zsh[tid] = z_local[b * Dv + tid];
        __syncthreads();
        float acc = b1[tid];
        #pragma unroll 8
        for (int k = 0; k < 256; ++k)
            acc = fmaf(zsh[k], Wp[k * Dv + tid], acc);
        g_base[b * Dv + tid] = acc;
        __syncthreads();
    }
}

// ---------------------------------------------------------------------------
// Persistent main kernel, 512 threads, fp16 m16n8k16. Fully pipelined:
// per-ks the mainloop of tile i carries (a) the GELU epilogue of tile i-1 and
// (b) the fp32->fp16 convert of tile i+1 (each thread converts exactly the
// bytes its own cp.async copied -> per-thread wait, no barrier). AH is
// double-buffered; S is single-buffered with a ~0.6-tile prefetch window.
// ---------------------------------------------------------------------------
__global__ void __launch_bounds__(512, 1) main_kernel(
    const float* __restrict__ nodes,
    const float* __restrict__ W2,
    const float* __restrict__ b2,
    const void*  __restrict__ batch,
    float* __restrict__ out, int C, int T)
{
    extern __shared__ float smem_f[];
    const uint32_t smem_base = smem_u32(smem_f);
    float* w2sh = smem_f + W2_OFF;
    float* red  = smem_f + RED_OFF;

    const int tid  = threadIdx.x;
    const int lane = tid & 31;
    const int warp = tid >> 5;
    const int wm   = warp >> 2;          // 0..3: rows wm*32
    const int wn   = warp & 3;           // 0..3: cols wn*32
    const int G    = gridDim.x;

    // ---- one-time Wh stage (34816 B = 2176 float4) ----
    {
        const float4* src = (const float4*)g_Wh;
        float4* dst = (float4*)(smem_f + WH_OFF);
        for (int idx = tid; idx < 2176; idx += 512) dst[idx] = src[idx];
        if (tid < 128) w2sh[tid] = W2[tid];
    }
    const float b2v  = b2[0];
    const int   is64 = g_is64;
    const int*       bt32 = (const int*)batch;
    const long long* bt64 = (const long long*)batch;

    // ---- ldmatrix lane addresses (fp16, pitch 272B) ----
    const int rowA = wm * 32 + (lane & 7) + ((lane >> 3) & 1) * 8;
    const uint32_t aA0 = smem_base + AH0_OFF * 4 + (uint32_t)rowA * 272
                       + ((lane >> 4) & 1) * 16;
    uint32_t bAdr[2];
    #pragma unroll
    for (int p = 0; p < 2; ++p) {
        const int nB = wn * 32 + p * 16 + (lane & 7) + ((lane >> 4) & 1) * 8;
        bAdr[p] = smem_base + WH_OFF * 4 + (uint32_t)nB * 272
                + ((lane >> 3) & 1) * 16;
    }

    auto issueA = [&](int t) {
        const int g0 = t * 128;
        int nr = C - g0; if (nr > 128) nr = 128;
        const char* src0 = (const char*)(nodes + (size_t)g0 * Dv);
        #pragma unroll
        for (int j = 0; j < 8; ++j) {
            const int e = j * 512 + tid;
            const int r = e >> 5, c = e & 31;
            if (r < nr) {
                const uint32_t dst = smem_base + (uint32_t)(r * 128 + c * 4) * 4;
                CP_ASYNC16(dst, src0 + (size_t)r * 512 + c * 16);
            }
        }
    };
    // convert one per-thread chunk j (0..7) of S into AH[wp]
    auto cvtChunk = [&](int wp, int j) {
        const int fi = j * 512 + tid;
        const int r = fi >> 5, c4 = fi & 31;
        const float4 v = ((const float4*)smem_f)[fi];
        uint2 hh;
        hh.x = pack_h2(v.x, v.y);
        hh.y = pack_h2(v.z, v.w);
        *(uint2*)((char*)smem_f + (AH0_OFF + wp * AH_STRIDE) * 4 + r * 272 + c4 * 8) = hh;
    };
    auto loadBidx = [&](int gr0, int bidx[2][2]) {
        #pragma unroll
        for (int tm = 0; tm < 2; ++tm)
            #pragma unroll
            for (int rh = 0; rh < 2; ++rh) {
                const int gr = gr0 + wm * 32 + tm * 16 + rh * 8 + (lane >> 2);
                bidx[tm][rh] = (gr < C) ? (is64 ? (int)bt64[gr] : bt32[gr]) : 0;
            }
    };
    auto finishEpi = [&](int pgr0, float pp[4]) {
        #pragma unroll
        for (int tm = 0; tm < 2; ++tm)
            #pragma unroll
            for (int rh = 0; rh < 2; ++rh) {
                float partial = pp[tm * 2 + rh];
                partial += __shfl_xor_sync(0xFFFFFFFFu, partial, 1);
                partial += __shfl_xor_sync(0xFFFFFFFFu, partial, 2);
                const int row = wm * 32 + tm * 16 + rh * 8 + (lane >> 2);
                if ((lane & 3) == 0) red[row * 4 + wn] = partial;
            }
        __syncthreads();
        if (tid < 128) {
            const int g2 = pgr0 + tid;
            if (g2 < C) {
                const float4 rv = *(const float4*)(red + tid * 4);
                out[g2] = rv.x + rv.y + rv.z + rv.w + b2v;
            }
        }
    };

    float accN[8][4], accO[8][4];
    int   pbidx[2][2];
    int   pgr0 = 0;
    const int n0base = wn * 32 + (lane & 3) * 2;

    int tile = blockIdx.x;
    if (tile >= T) return;

    // ---- prologue: stage + convert first tile serially; prefetch tile+G ----
    issueA(tile);
    CP_COMMIT();
    CP_WAIT0();
    #pragma unroll
    for (int j = 0; j < 8; ++j) cvtChunk(0, j);
    __syncthreads();
    if (tile + G < T) issueA(tile + G);
    CP_COMMIT();

    int ahp = 0;
    int doEpi = 0;

    for (; tile < T; tile += G) {
        int bidx[2][2];
        loadBidx(tile * 128, bidx);

        #pragma unroll
        for (int n = 0; n < 8; ++n)
            #pragma unroll
            for (int i = 0; i < 4; ++i) accN[n][i] = 0.f;

        float pp[4] = {0.f, 0.f, 0.f, 0.f};
        const uint32_t aA = aA0 + (uint32_t)ahp * (AH_STRIDE * 4);
        const int wp = ahp ^ 1;
        const int cvtNext = (tile + G < T);

        #pragma unroll
        for (int ks = 0; ks < 8; ++ks) {
            uint32_t a0[4], a1[4], u0[4], u1[4];
            LDSM_X4(a0[0], a0[1], a0[2], a0[3], aA + ks * 32);
            LDSM_X4(a1[0], a1[1], a1[2], a1[3], aA + ks * 32 + 16 * 272);
            LDSM_X4(u0[0], u0[1], u0[2], u0[3], bAdr[0] + ks * 32);
            LDSM_X4(u1[0], u1[1], u1[2], u1[3], bAdr[1] + ks * 32);

            // epilogue chunk of tile i-1: tm = ks>>2, nt = ks&3
            if (doEpi) {
                const int tm = ks >> 2, nt = ks & 3;
                const int n0 = n0base + nt * 8;
                const float2 w2v = *(const float2*)(w2sh + n0);
                const float2 bv0 = __ldg((const float2*)(g_base + pbidx[tm][0] * Dv + n0));
                const float2 bv1 = __ldg((const float2*)(g_base + pbidx[tm][1] * Dv + n0));
                const float x0 = accO[tm * 4 + nt][0] + bv0.x;
                const float x1 = accO[tm * 4 + nt][1] + bv0.y;
                const float x2 = accO[tm * 4 + nt][2] + bv1.x;
                const float x3 = accO[tm * 4 + nt][3] + bv1.y;
                pp[tm * 2 + 0] = fmaf(gelu_fast(x0), w2v.x, pp[tm * 2 + 0]);
                pp[tm * 2 + 0] = fmaf(gelu_fast(x1), w2v.y, pp[tm * 2 + 0]);
                pp[tm * 2 + 1] = fmaf(gelu_fast(x2), w2v.x, pp[tm * 2 + 1]);
                pp[tm * 2 + 1] = fmaf(gelu_fast(x3), w2v.y, pp[tm * 2 + 1]);
            }

            // convert chunks of tile i+1 (own cp.async bytes -> no barrier)
            if (ks == 4) CP_WAIT0();
            if (ks >= 4 && cvtNext) {
                cvtChunk(wp, (ks - 4) * 2 + 0);
                cvtChunk(wp, (ks - 4) * 2 + 1);
            }

            MMA_F16(accN[0], a0, u0[0], u0[1]);
            MMA_F16(accN[1], a0, u0[2], u0[3]);
            MMA_F16(accN[2], a0, u1[0], u1[1]);
            MMA_F16(accN[3], a0, u1[2], u1[3]);
            MMA_F16(accN[4], a1, u0[0], u0[1]);
            MMA_F16(accN[5], a1, u0[2], u0[3]);
            MMA_F16(accN[6], a1, u1[0], u1[1]);
            MMA_F16(accN[7], a1, u1[2], u1[3]);
        }

        // S is consumed; prefetch tile i+2 (window ~= 60% of a tile)
        if (tile + 2 * G < T) issueA(tile + 2 * G);
        CP_COMMIT();

        if (doEpi) finishEpi(pgr0, pp);
        else       __syncthreads();      // publish AH[wp] for the next body

        #pragma unroll
        for (int n = 0; n < 8; ++n)
            #pragma unroll
            for (int i = 0; i < 4; ++i) accO[n][i] = accN[n][i];
        pbidx[0][0] = bidx[0][0]; pbidx[0][1] = bidx[0][1];
        pbidx[1][0] = bidx[1][0]; pbidx[1][1] = bidx[1][1];
        pgr0 = tile * 128;
        doEpi = 1;
        ahp ^= 1;
    }

    // ---- drain: standalone epilogue for the last tile ----
    {
        float pp[4] = {0.f, 0.f, 0.f, 0.f};
        #pragma unroll
        for (int ks = 0; ks < 8; ++ks) {
            const int tm = ks >> 2, nt = ks & 3;
            const int n0 = n0base + nt * 8;
            const float2 w2v = *(const float2*)(w2sh + n0);
            const float2 bv0 = __ldg((const float2*)(g_base + pbidx[tm][0] * Dv + n0));
            const float2 bv1 = __ldg((const float2*)(g_base + pbidx[tm][1] * Dv + n0));
            const float x0 = accO[tm * 4 + nt][0] + bv0.x;
            const float x1 = accO[tm * 4 + nt][1] + bv0.y;
            const float x2 = accO[tm * 4 + nt][2] + bv1.x;
            const float x3 = accO[tm * 4 + nt][3] + bv1.y;
            pp[tm * 2 + 0] = fmaf(gelu_fast(x0), w2v.x, pp[tm * 2 + 0]);
            pp[tm * 2 + 0] = fmaf(gelu_fast(x1), w2v.y, pp[tm * 2 + 0]);
            pp[tm * 2 + 1] = fmaf(gelu_fast(x2), w2v.x, pp[tm * 2 + 1]);
            pp[tm * 2 + 1] = fmaf(gelu_fast(x3), w2v.y, pp[tm * 2 + 1]);
        }
        __syncthreads();
        finishEpi(pgr0, pp);
    }
}

// ---------------------------------------------------------------------------
extern "C" void kernel_launch(void* const* d_in, const int* in_sizes, int n_in,
                              void* d_out, int out_size)
{
    const float* nodes   = (const float*)d_in[0];
    const float* z_local = (const float*)d_in[1];
    const float* z_meta  = (const float*)d_in[2];
    const float* W1      = (const float*)d_in[3];
    const float* b1      = (const float*)d_in[4];
    const float* W2      = (const float*)d_in[5];
    const float* b2      = (const float*)d_in[6];
    const void*  batch   = d_in[7];
    float* out = (float*)d_out;

    const int C = in_sizes[7];
    const int B = in_sizes[1] / Dv;
    const int T = (C + 127) / 128;

    int dev = 0, nsm = 148;
    cudaGetDevice(&dev);
    cudaDeviceGetAttribute(&nsm, cudaDevAttrMultiProcessorCount, dev);

    const int PREP_SMEM = (256 * Dv + 256) * (int)sizeof(float);   // 132096
    const int MAIN_SMEM = SMEM_WORDS * (int)sizeof(float);         // 172544

    cudaFuncSetAttribute(prep_kernel, cudaFuncAttributeMaxDynamicSharedMemorySize, PREP_SMEM);
    cudaFuncSetAttribute(main_kernel, cudaFuncAttributeMaxDynamicSharedMemorySize, MAIN_SMEM);

    aux_kernel<<<65, 256>>>(W1, (const int*)batch, C);
    prep_kernel<<<B / 32, 128, PREP_SMEM>>>(z_local, z_meta, W1, b1);

    main_kernel<<<nsm, 512, MAIN_SMEM>>>(nodes, W2, b2, batch, out, C, T);
}

// round 12
// speedup vs baseline: 5.3855x; 1.0416x over previous
#include <cuda_runtime.h>
#include <cuda_fp16.h>
#include <math.h>
#include <stdint.h>

#define Dv   128
#define Bv   4096

// SMEM word layout (main kernel)
#define S_OFF     0                       // fp32 stage: 128x128 (cp.async target)
#define AH0_OFF   16384                   // fp16 A tile 0: 128 x 136 halves (272B pitch)
#define AH_STRIDE 8704                    // words per AH buffer (34816 B)
#define AH1_OFF   (AH0_OFF + AH_STRIDE)   // 25088
#define WH_OFF    (AH1_OFF + AH_STRIDE)   // 33792
#define W2_OFF    (WH_OFF + AH_STRIDE)    // 42496
#define RED_OFF   (W2_OFF + 128)          // 42624
#define SMEM_WORDS (RED_OFF + 512)        // 43136 -> 172544 B

// Scratch globals
__device__ float g_base[Bv * Dv];                 // per-graph base rows (2 MB)
__device__ __align__(16) __half g_Wh[128 * 136];  // W1a^T fp16, pitch 136 halves
__device__ int   g_is64;

// ---------------- helpers ----------------
__device__ __forceinline__ uint32_t smem_u32(const void* p) {
    uint32_t a;
    asm("{ .reg .u64 t; cvta.to.shared.u64 t, %1; cvt.u32.u64 %0, t; }" : "=r"(a) : "l"(p));
    return a;
}
__device__ __forceinline__ uint32_t pack_h2(float lo, float hi) {
    uint32_t r;
    asm("cvt.rn.f16x2.f32 %0, %1, %2;" : "=r"(r) : "f"(hi), "f"(lo));
    return r;
}
#define CP_ASYNC16(dst, src) \
    asm volatile("cp.async.cg.shared.global [%0], [%1], 16;" :: "r"(dst), "l"(src) : "memory")
#define CP_COMMIT() asm volatile("cp.async.commit_group;" ::: "memory")
#define CP_WAIT0()  asm volatile("cp.async.wait_group 0;" ::: "memory")

#define LDSM_X4(r0, r1, r2, r3, addr)                                          \
    asm volatile("ldmatrix.sync.aligned.m8n8.x4.shared.b16 {%0,%1,%2,%3}, [%4];" \
        : "=r"(r0), "=r"(r1), "=r"(r2), "=r"(r3) : "r"(addr))

// mma.sync m16n8k16 fp16 -> fp32 accum
#define MMA_F16(c, a, b0_, b1_)                                                \
    asm volatile(                                                              \
        "mma.sync.aligned.m16n8k16.row.col.f32.f16.f16.f32 "                   \
        "{%0,%1,%2,%3}, {%4,%5,%6,%7}, {%8,%9}, {%0,%1,%2,%3};"                \
        : "+f"((c)[0]), "+f"((c)[1]), "+f"((c)[2]), "+f"((c)[3])               \
        : "r"((a)[0]), "r"((a)[1]), "r"((a)[2]), "r"((a)[3]),                  \
          "r"(b0_), "r"(b1_))

// gelu(x) = 0.5x(1+tanh(0.79788456x + 0.03567741x^3)) -- single MUFU tanh
__device__ __forceinline__ float gelu_fast(float x) {
    const float z = x * fmaf(0.035677408f, x * x, 0.7978845608f);
    float t;
    asm("tanh.approx.f32 %0, %1;" : "=f"(t) : "f"(z));
    const float hx = 0.5f * x;
    return fmaf(hx, t, hx);
}

// ---------------------------------------------------------------------------
// aux: blocks 0..63 build g_Wh = fp16(W1a^T) at pitch 136;
//      block 64 detects batch dtype (word [C-1] is 0 iff int64).
// ---------------------------------------------------------------------------
__global__ void __launch_bounds__(256) aux_kernel(const float* __restrict__ W1,
                                                  const int* __restrict__ batch_words,
                                                  int C) {
    if (blockIdx.x == 64) {
        if (threadIdx.x == 0) g_is64 = (batch_words[C - 1] == 0) ? 1 : 0;
        return;
    }
    const int idx = blockIdx.x * 256 + threadIdx.x;   // 16384
    const int n = idx >> 7, k = idx & 127;
    g_Wh[n * 136 + k] = __float2half_rn(W1[k * Dv + n]);
}

// base[b][d] = b1[d] + z_local[b]·W1[128:256] + z_meta·W1[256:384]
// 4 partial accumulators break the FMA dependency chain (4x ILP).
__global__ void __launch_bounds__(128) prep_kernel(
    const float* __restrict__ z_local, const float* __restrict__ z_meta,
    const float* __restrict__ W1, const float* __restrict__ b1)
{
    extern __shared__ float smem_f[];
    float* Wp  = smem_f;
    float* zsh = smem_f + 256 * Dv;
    const int tid = threadIdx.x;

    const float4* Wsrc = (const float4*)(W1 + Dv * Dv);
    float4* Wdst = (float4*)Wp;
    for (int i = tid; i < 256 * Dv / 4; i += 128) Wdst[i] = Wsrc[i];
    zsh[Dv + tid] = z_meta[tid];
    __syncthreads();

    const int b0 = blockIdx.x * 32;
    for (int g = 0; g < 32; ++g) {
        const int b = b0 + g;
        zsh[tid] = z_local[b * Dv + tid];
        __syncthreads();
        float a0 = 0.f, a1 = 0.f, a2 = 0.f, a3 = 0.f;
        #pragma unroll 4
        for (int k = 0; k < 256; k += 4) {
            a0 = fmaf(zsh[k + 0], Wp[(k + 0) * Dv + tid], a0);
            a1 = fmaf(zsh[k + 1], Wp[(k + 1) * Dv + tid], a1);
            a2 = fmaf(zsh[k + 2], Wp[(k + 2) * Dv + tid], a2);
            a3 = fmaf(zsh[k + 3], Wp[(k + 3) * Dv + tid], a3);
        }
        g_base[b * Dv + tid] = b1[tid] + ((a0 + a1) + (a2 + a3));
        __syncthreads();
    }
}

// ---------------------------------------------------------------------------
// Persistent main kernel, 512 threads, fp16 m16n8k16, fully pipelined:
// per-ks the mainloop of tile i carries the GELU epilogue of tile i-1 (with
// its g_base loads register-prefetched at distance 2) and the fp32->fp16
// convert of tile i+1 (own cp.async bytes -> per-thread wait, no barrier).
// ---------------------------------------------------------------------------
__global__ void __launch_bounds__(512, 1) main_kernel(
    const float* __restrict__ nodes,
    const float* __restrict__ W2,
    const float* __restrict__ b2,
    const void*  __restrict__ batch,
    float* __restrict__ out, int C, int T)
{
    extern __shared__ float smem_f[];
    const uint32_t smem_base = smem_u32(smem_f);
    float* w2sh = smem_f + W2_OFF;
    float* red  = smem_f + RED_OFF;

    const int tid  = threadIdx.x;
    const int lane = tid & 31;
    const int warp = tid >> 5;
    const int wm   = warp >> 2;          // 0..3: rows wm*32
    const int wn   = warp & 3;           // 0..3: cols wn*32
    const int G    = gridDim.x;

    // ---- one-time Wh stage (34816 B = 2176 float4) ----
    {
        const float4* src = (const float4*)g_Wh;
        float4* dst = (float4*)(smem_f + WH_OFF);
        for (int idx = tid; idx < 2176; idx += 512) dst[idx] = src[idx];
        if (tid < 128) w2sh[tid] = W2[tid];
    }
    const float b2v  = b2[0];
    const int   is64 = g_is64;
    const int*       bt32 = (const int*)batch;
    const long long* bt64 = (const long long*)batch;

    // ---- ldmatrix lane addresses (fp16, pitch 272B) ----
    const int rowA = wm * 32 + (lane & 7) + ((lane >> 3) & 1) * 8;
    const uint32_t aA0 = smem_base + AH0_OFF * 4 + (uint32_t)rowA * 272
                       + ((lane >> 4) & 1) * 16;
    uint32_t bAdr[2];
    #pragma unroll
    for (int p = 0; p < 2; ++p) {
        const int nB = wn * 32 + p * 16 + (lane & 7) + ((lane >> 4) & 1) * 8;
        bAdr[p] = smem_base + WH_OFF * 4 + (uint32_t)nB * 272
                + ((lane >> 3) & 1) * 16;
    }

    auto issueA = [&](int t) {
        const int g0 = t * 128;
        int nr = C - g0; if (nr > 128) nr = 128;
        const char* src0 = (const char*)(nodes + (size_t)g0 * Dv);
        #pragma unroll
        for (int j = 0; j < 8; ++j) {
            const int e = j * 512 + tid;
            const int r = e >> 5, c = e & 31;
            if (r < nr) {
                const uint32_t dst = smem_base + (uint32_t)(r * 128 + c * 4) * 4;
                CP_ASYNC16(dst, src0 + (size_t)r * 512 + c * 16);
            }
        }
    };
    auto cvtChunk = [&](int wp, int j) {
        const int fi = j * 512 + tid;
        const int r = fi >> 5, c4 = fi & 31;
        const float4 v = ((const float4*)smem_f)[fi];
        uint2 hh;
        hh.x = pack_h2(v.x, v.y);
        hh.y = pack_h2(v.z, v.w);
        *(uint2*)((char*)smem_f + (AH0_OFF + wp * AH_STRIDE) * 4 + r * 272 + c4 * 8) = hh;
    };
    auto loadBidx = [&](int gr0, int bidx[2][2]) {
        #pragma unroll
        for (int tm = 0; tm < 2; ++tm)
            #pragma unroll
            for (int rh = 0; rh < 2; ++rh) {
                const int gr = gr0 + wm * 32 + tm * 16 + rh * 8 + (lane >> 2);
                bidx[tm][rh] = (gr < C) ? (is64 ? (int)bt64[gr] : bt32[gr]) : 0;
            }
    };
    auto finishEpi = [&](int pgr0, float pp[4]) {
        #pragma unroll
        for (int tm = 0; tm < 2; ++tm)
            #pragma unroll
            for (int rh = 0; rh < 2; ++rh) {
                float partial = pp[tm * 2 + rh];
                partial += __shfl_xor_sync(0xFFFFFFFFu, partial, 1);
                partial += __shfl_xor_sync(0xFFFFFFFFu, partial, 2);
                const int row = wm * 32 + tm * 16 + rh * 8 + (lane >> 2);
                if ((lane & 3) == 0) red[row * 4 + wn] = partial;
            }
        __syncthreads();
        if (tid < 128) {
            const int g2 = pgr0 + tid;
            if (g2 < C) {
                const float4 rv = *(const float4*)(red + tid * 4);
                out[g2] = rv.x + rv.y + rv.z + rv.w + b2v;
            }
        }
    };

    float accN[8][4], accO[8][4];
    int   pbidx[2][2];
    int   pgr0 = 0;
    const int n0base = wn * 32 + (lane & 3) * 2;

    // base-load register ring (distance-2 prefetch), per chunk: rows rh0/rh1
    auto ldBase = [&](int chunk, float2& o0, float2& o1) {
        const int tm = chunk >> 2, nt = chunk & 3;
        const int n0 = n0base + nt * 8;
        o0 = __ldg((const float2*)(g_base + pbidx[tm][0] * Dv + n0));
        o1 = __ldg((const float2*)(g_base + pbidx[tm][1] * Dv + n0));
    };

    int tile = blockIdx.x;
    if (tile >= T) return;

    // ---- prologue: stage + convert first tile serially; prefetch tile+G ----
    issueA(tile);
    CP_COMMIT();
    CP_WAIT0();
    #pragma unroll
    for (int j = 0; j < 8; ++j) cvtChunk(0, j);
    __syncthreads();
    if (tile + G < T) issueA(tile + G);
    CP_COMMIT();

    int ahp = 0;
    int doEpi = 0;

    for (; tile < T; tile += G) {
        int bidx[2][2];
        loadBidx(tile * 128, bidx);

        #pragma unroll
        for (int n = 0; n < 8; ++n)
            #pragma unroll
            for (int i = 0; i < 4; ++i) accN[n][i] = 0.f;

        float pp[4] = {0.f, 0.f, 0.f, 0.f};
        const uint32_t aA = aA0 + (uint32_t)ahp * (AH_STRIDE * 4);
        const int wp = ahp ^ 1;
        const int cvtNext = (tile + G < T);

        // preload base values for epilogue chunks 0 and 1 (slots 0/1)
        float2 bvA0, bvA1, bvB0, bvB1;
        if (doEpi) { ldBase(0, bvA0, bvA1); ldBase(1, bvB0, bvB1); }

        #pragma unroll
        for (int ks = 0; ks < 8; ++ks) {
            uint32_t a0[4], a1[4], u0[4], u1[4];
            LDSM_X4(a0[0], a0[1], a0[2], a0[3], aA + ks * 32);
            LDSM_X4(a1[0], a1[1], a1[2], a1[3], aA + ks * 32 + 16 * 272);
            LDSM_X4(u0[0], u0[1], u0[2], u0[3], bAdr[0] + ks * 32);
            LDSM_X4(u1[0], u1[1], u1[2], u1[3], bAdr[1] + ks * 32);

            // epilogue chunk ks of tile i-1 (base values prefetched 2 iters ago)
            if (doEpi) {
                const int tm = ks >> 2, nt = ks & 3;
                const int n0 = n0base + nt * 8;
                const float2 w2v = *(const float2*)(w2sh + n0);
                const float2 bv0 = (ks & 1) ? bvB0 : bvA0;
                const float2 bv1 = (ks & 1) ? bvB1 : bvA1;
                const float x0 = accO[tm * 4 + nt][0] + bv0.x;
                const float x1 = accO[tm * 4 + nt][1] + bv0.y;
                const float x2 = accO[tm * 4 + nt][2] + bv1.x;
                const float x3 = accO[tm * 4 + nt][3] + bv1.y;
                pp[tm * 2 + 0] = fmaf(gelu_fast(x0), w2v.x, pp[tm * 2 + 0]);
                pp[tm * 2 + 0] = fmaf(gelu_fast(x1), w2v.y, pp[tm * 2 + 0]);
                pp[tm * 2 + 1] = fmaf(gelu_fast(x2), w2v.x, pp[tm * 2 + 1]);
                pp[tm * 2 + 1] = fmaf(gelu_fast(x3), w2v.y, pp[tm * 2 + 1]);
                // prefetch chunk ks+2 into the slot just consumed
                if (ks < 6) {
                    if (ks & 1) ldBase(ks + 2, bvB0, bvB1);
                    else        ldBase(ks + 2, bvA0, bvA1);
                }
            }

            // convert chunks of tile i+1 (own cp.async bytes -> no barrier)
            if (ks == 4) CP_WAIT0();
            if (ks >= 4 && cvtNext) {
                cvtChunk(wp, (ks - 4) * 2 + 0);
                cvtChunk(wp, (ks - 4) * 2 + 1);
            }

            MMA_F16(accN[0], a0, u0[0], u0[1]);
            MMA_F16(accN[1], a0, u0[2], u0[3]);
            MMA_F16(accN[2], a0, u1[0], u1[1]);
            MMA_F16(accN[3], a0, u1[2], u1[3]);
            MMA_F16(accN[4], a1, u0[0], u0[1]);
            MMA_F16(accN[5], a1, u0[2], u0[3]);
            MMA_F16(accN[6], a1, u1[0], u1[1]);
            MMA_F16(accN[7], a1, u1[2], u1[3]);
        }

        // S is consumed; prefetch tile i+2
        if (tile + 2 * G < T) issueA(tile + 2 * G);
        CP_COMMIT();

        if (doEpi) finishEpi(pgr0, pp);
        else       __syncthreads();      // publish AH[wp] for the next body

        #pragma unroll
        for (int n = 0; n < 8; ++n)
            #pragma unroll
            for (int i = 0; i < 4; ++i) accO[n][i] = accN[n][i];
        pbidx[0][0] = bidx[0][0]; pbidx[0][1] = bidx[0][1];
        pbidx[1][0] = bidx[1][0]; pbidx[1][1] = bidx[1][1];
        pgr0 = tile * 128;
        doEpi = 1;
        ahp ^= 1;
    }

    // ---- drain: standalone epilogue for the last tile ----
    {
        float pp[4] = {0.f, 0.f, 0.f, 0.f};
        #pragma unroll
        for (int ks = 0; ks < 8; ++ks) {
            const int tm = ks >> 2, nt = ks & 3;
            const int n0 = n0base + nt * 8;
            const float2 w2v = *(const float2*)(w2sh + n0);
            const float2 bv0 = __ldg((const float2*)(g_base + pbidx[tm][0] * Dv + n0));
            const float2 bv1 = __ldg((const float2*)(g_base + pbidx[tm][1] * Dv + n0));
            const float x0 = accO[tm * 4 + nt][0] + bv0.x;
            const float x1 = accO[tm * 4 + nt][1] + bv0.y;
            const float x2 = accO[tm * 4 + nt][2] + bv1.x;
            const float x3 = accO[tm * 4 + nt][3] + bv1.y;
            pp[tm * 2 + 0] = fmaf(gelu_fast(x0), w2v.x, pp[tm * 2 + 0]);
            pp[tm * 2 + 0] = fmaf(gelu_fast(x1), w2v.y, pp[tm * 2 + 0]);
            pp[tm * 2 + 1] = fmaf(gelu_fast(x2), w2v.x, pp[tm * 2 + 1]);
            pp[tm * 2 + 1] = fmaf(gelu_fast(x3), w2v.y, pp[tm * 2 + 1]);
        }
        __syncthreads();
        finishEpi(pgr0, pp);
    }
}

// ---------------------------------------------------------------------------
extern "C" void kernel_launch(void* const* d_in, const int* in_sizes, int n_in,
                              void* d_out, int out_size)
{
    const float* nodes   = (const float*)d_in[0];
    const float* z_local = (const float*)d_in[1];
    const float* z_meta  = (const float*)d_in[2];
    const float* W1      = (const float*)d_in[3];
    const float* b1      = (const float*)d_in[4];
    const float* W2      = (const float*)d_in[5];
    const float* b2      = (const float*)d_in[6];
    const void*  batch   = d_in[7];
    float* out = (float*)d_out;

    const int C = in_sizes[7];
    const int B = in_sizes[1] / Dv;
    const int T = (C + 127) / 128;

    int dev = 0, nsm = 148;
    cudaGetDevice(&dev);
    cudaDeviceGetAttribute(&nsm, cudaDevAttrMultiProcessorCount, dev);

    const int PREP_SMEM = (256 * Dv + 256) * (int)sizeof(float);   // 132096
    const int MAIN_SMEM = SMEM_WORDS * (int)sizeof(float);         // 172544

    cudaFuncSetAttribute(prep_kernel, cudaFuncAttributeMaxDynamicSharedMemorySize, PREP_SMEM);
    cudaFuncSetAttribute(main_kernel, cudaFuncAttributeMaxDynamicSharedMemorySize, MAIN_SMEM);

    aux_kernel<<<65, 256>>>(W1, (const int*)batch, C);
    prep_kernel<<<B / 32, 128, PREP_SMEM>>>(z_local, z_meta, W1, b1);

    main_kernel<<<nsm, 512, MAIN_SMEM>>>(nodes, W2, b2, batch, out, C, T);
}